// round 8
// baseline (speedup 1.0000x reference)
#include <cuda_runtime.h>
#include <cuda_bf16.h>
#include <math.h>
#include <cstdint>

// ---------------------------------------------------------------------------
// DAFCN forward, B=1024, T=50, F=48, D=512.
// Attention branch (wq*/wk*, dvb, attended) dead: combined[:,:,:10] = gcn_out.
// R8: reassociate att@(X@W) = (att@X)@W. Per layer:
//   att_z   : Z = att @ X        (CUDA cores, f32x2, emits bf16 hi/lo)
//   gemm    : Y = tanh(Z@W + b) [+ residual]   (bf16x3 HMMA, fused epilogue)
// Heads: prep_w / ffc / gc1.  Tail: gc7 + fused + MLP.
// ---------------------------------------------------------------------------

typedef unsigned long long ull;

#define PI_F 3.14159265358979f
#define W0_DCT 0.18257418583505537f
#define W1_DCT 0.2581988897471611f
#define NB 1024
#define MROWS (NB * 48)

__device__ float         g_X[MROWS * 512];      // fp32 y (and final y)
__device__ float         g_H[MROWS * 512];      // fp32 h (stage intermediate)
__device__ __nv_bfloat16 g_Zhi[MROWS * 512];    // gemm A operand hi
__device__ __nv_bfloat16 g_Zlo[MROWS * 512];    // gemm A operand lo
__device__ __nv_bfloat16 g_Whi[4 * 512 * 512];  // W^T [l][n][k] hi
__device__ __nv_bfloat16 g_Wlo[4 * 512 * 512];  // W^T [l][n][k] lo
__device__ float         g_dct[NB * 480];
__device__ float         g_ffc[NB * 480];

// ---- packed f32x2 helpers -------------------------------------------------
__device__ __forceinline__ ull pk2(float lo, float hi) {
    ull r; asm("mov.b64 %0, {%1, %2};" : "=l"(r) : "f"(lo), "f"(hi)); return r;
}
__device__ __forceinline__ void fma2f(ull &d, ull a, ull b) {
    asm("fma.rn.f32x2 %0, %1, %2, %0;" : "+l"(d) : "l"(a), "l"(b));
}
__device__ __forceinline__ float2 up2(ull v) {
    float lo, hi; asm("mov.b64 {%0, %1}, %2;" : "=f"(lo), "=f"(hi) : "l"(v));
    return make_float2(lo, hi);
}
__device__ __forceinline__ uint32_t smem_u32(const void* p) {
    uint32_t a;
    asm("{ .reg .u64 t; cvta.to.shared.u64 t, %1; cvt.u32.u64 %0, t; }"
        : "=r"(a) : "l"(p));
    return a;
}

#define CPA16(dst, src) \
    asm volatile("cp.async.cg.shared.global [%0], [%1], 16;" \
                 :: "r"(dst), "l"(src))
#define CP_COMMIT() asm volatile("cp.async.commit_group;" ::: "memory")
#define CP_WAIT(n)  asm volatile("cp.async.wait_group %0;" :: "n"(n) : "memory")

#define LDSM4(r, addr) \
    asm volatile("ldmatrix.sync.aligned.m8n8.x4.shared.b16 {%0,%1,%2,%3}, [%4];" \
        : "=r"((r)[0]), "=r"((r)[1]), "=r"((r)[2]), "=r"((r)[3]) : "r"(addr))

__device__ __forceinline__ void mma_bf16(float* d, const uint32_t* a,
                                         const uint32_t* b) {
    asm volatile(
        "mma.sync.aligned.m16n8k16.row.col.f32.bf16.bf16.f32 "
        "{%0,%1,%2,%3}, {%4,%5,%6,%7}, {%8,%9}, {%0,%1,%2,%3};"
        : "+f"(d[0]), "+f"(d[1]), "+f"(d[2]), "+f"(d[3])
        : "r"(a[0]), "r"(a[1]), "r"(a[2]), "r"(a[3]), "r"(b[0]), "r"(b[1]));
}

// ======================= prep_w: W^T bf16 hi/lo ============================
__global__ void prep_w_kernel(const float* __restrict__ gcb_w) {
    int idx = blockIdx.x * 256 + threadIdx.x;      // 4*512*512
    int l = idx >> 18, k = (idx >> 9) & 511, n = idx & 511;
    float w = gcb_w[l * 262144 + k * 512 + n];
    __nv_bfloat16 hi = __float2bfloat16(w);
    __nv_bfloat16 lo = __float2bfloat16(w - __bfloat162float(hi));
    int dst = l * 262144 + n * 512 + k;
    g_Whi[dst] = hi; g_Wlo[dst] = lo;
}

// ======================= FFC ===============================================
__global__ void ffc_kernel(const float* __restrict__ seq,
                           const float* __restrict__ wl,
                           const float* __restrict__ wg) {
    int bx = blockIdx.x, b = bx >> 4, g = bx & 15, tid = threadIdx.x;
    __shared__ float sXf[3][60], sV[6][31], sc[60], ss[60], sWg[36], sWl[9];
    if (tid < 60) {
        float a = 6.283185307179586f * (float)tid / 60.0f;
        sc[tid] = cosf(a); ss[tid] = sinf(a);
    }
    if (tid < 36) sWg[tid] = wg[tid];
    if (tid < 9)  sWl[tid] = wl[tid];
    for (int i = tid; i < 180; i += 64) {
        int c = i / 60, t = i % 60, tsrc = (t < 50) ? t : 49;
        sXf[c][t] = seq[b * 2400 + tsrc * 48 + c * 16 + g];
    }
    __syncthreads();
    if (tid < 31) {
        int k = tid;
        float re0=0,re1=0,re2=0,im0=0,im1=0,im2=0; int idx = 0;
        for (int t = 0; t < 60; t++) {
            float co = sc[idx], si = ss[idx];
            float x0 = sXf[0][t], x1 = sXf[1][t], x2 = sXf[2][t];
            re0 += x0*co; im0 -= x0*si; re1 += x1*co; im1 -= x1*si;
            re2 += x2*co; im2 -= x2*si;
            idx += k; if (idx >= 60) idx -= 60;
        }
        float U[6] = {re0, re1, re2, im0, im1, im2};
        #pragma unroll
        for (int o = 0; o < 6; o++) {
            float a = 0.f;
            #pragma unroll
            for (int c = 0; c < 6; c++) a += sWg[o * 6 + c] * U[c];
            sV[o][k] = (a > 0.f) ? a : 0.f;
        }
    }
    __syncthreads();
    if (tid < 30) {
        int o = tid / 10, t = tid % 10;
        float spec = sV[o][0] + ((t & 1) ? -sV[o][30] : sV[o][30]);
        int idx = t;
        for (int k = 1; k < 30; k++) {
            spec += 2.0f * (sV[o][k] * sc[idx] - sV[o + 3][k] * ss[idx]);
            idx += t; if (idx >= 60) idx -= 60;
        }
        float v = spec * (1.0f / 60.0f);
        #pragma unroll
        for (int c = 0; c < 3; c++) v += sWl[o * 3 + c] * sXf[c][t];
        g_ffc[b * 480 + (o * 16 + g) * 10 + t] = v;
    }
}

// ======================= gc1 head: y0 -> g_X ===============================
__global__ void __launch_bounds__(512)
gc1_kernel(const float* __restrict__ seq, const float* __restrict__ gc1_w,
           const float* __restrict__ gc1_att, const float* __restrict__ gc1_b) {
    __shared__ float sDct[480], sZ1[480];
    const int tid = threadIdx.x, b = blockIdx.x;
    const float* sq = seq + b * 2400;
    if (tid < 480) {
        int f = tid % 48, d = tid / 48;
        float wd = (d == 0) ? W0_DCT : W1_DCT;
        float acc = 0.f, Sd = 0.f;
        for (int k = 0; k < 30; k++) {
            float cv = wd * cosf(PI_F * ((float)k + 0.5f) * (float)d / 30.0f);
            if (k < 10) acc += cv * sq[(40 + k) * 48 + f];
            else        Sd  += cv;
        }
        acc += Sd * sq[49 * 48 + f];
        sDct[f * 10 + d] = acc;
        g_dct[b * 480 + f * 10 + d] = acc;
    }
    __syncthreads();
    if (tid < 480) {
        int n = tid / 10, d = tid % 10;
        float a = 0.f;
        for (int m = 0; m < 48; m++) a += __ldg(gc1_att + n * 48 + m) * sDct[m * 10 + d];
        sZ1[n * 10 + d] = a;
    }
    __syncthreads();
    float w10[10];
    #pragma unroll
    for (int d = 0; d < 10; d++) w10[d] = __ldg(gc1_w + d * 512 + tid);
    float bb = __ldg(gc1_b + tid);
    for (int n = 0; n < 48; n++) {
        float a = bb;
        #pragma unroll
        for (int d = 0; d < 10; d++) a += w10[d] * sZ1[n * 10 + d];
        g_X[(size_t)(b * 48 + n) * 512 + tid] = tanhf(a);
    }
}

// ======================= att_z: Z = att @ src, emit bf16 hi/lo =============
__global__ void __launch_bounds__(512)
att_z_kernel(const float* __restrict__ att, int src_is_x) {
    __shared__ float sAttT[2304];      // [m][n], n contiguous
    const int b = blockIdx.x, c = threadIdx.x;
    for (int i = c; i < 2304; i += 512) {
        int m = i / 48, n = i % 48;
        sAttT[m * 48 + n] = att[n * 48 + m];
    }
    __syncthreads();

    const float* src = (src_is_x ? g_X : g_H) + (size_t)b * 48 * 512 + c;
    float g[48];
    #pragma unroll
    for (int m = 0; m < 48; m++) g[m] = src[(size_t)m * 512];

    ull acc[24];
    #pragma unroll
    for (int i = 0; i < 24; i++) acc[i] = 0ull;

    #pragma unroll 4
    for (int m = 0; m < 48; m++) {
        ull gp = pk2(g[m], g[m]);
        const ull* ar = (const ull*)(sAttT + m * 48);
        #pragma unroll
        for (int np = 0; np < 24; np++) fma2f(acc[np], ar[np], gp);
    }

    __nv_bfloat16* Zh = g_Zhi + (size_t)b * 48 * 512 + c;
    __nv_bfloat16* Zl = g_Zlo + (size_t)b * 48 * 512 + c;
    #pragma unroll
    for (int np = 0; np < 24; np++) {
        float2 z = up2(acc[np]);
        __nv_bfloat16 h0 = __float2bfloat16(z.x);
        __nv_bfloat16 h1 = __float2bfloat16(z.y);
        size_t i0 = (size_t)(2 * np) * 512, i1 = i0 + 512;
        Zh[i0] = h0; Zl[i0] = __float2bfloat16(z.x - __bfloat162float(h0));
        Zh[i1] = h1; Zl[i1] = __float2bfloat16(z.y - __bfloat162float(h1));
    }
}

// ======================= bf16x3 HMMA GEMM + fused epilogue =================
// Y[m][n] = tanh(sum_k Z[m][k] Wt[n][k] + bias[n]) (+ g_X residual).
// CTA 128x128, 8 warps (2x4), warp 64x32; grid (4 n-tiles, 384 m-tiles).
#define A_STRIDE 40
#define MAT_SZ (128 * A_STRIDE)
#define GEMM_SMEM (2 * 4 * MAT_SZ * 2)   // 81920 B

__global__ void __launch_bounds__(256, 1)
gemm_kernel(int layer, int residual, int dst_is_x,
            const float* __restrict__ bias) {
    extern __shared__ __align__(16) __nv_bfloat16 smem[];
    const int tid = threadIdx.x;
    const int lane = tid & 31, wid = tid >> 5;
    const int wm = wid >> 2, wn = wid & 3;
    const int n0 = blockIdx.x * 128;
    const int m0 = blockIdx.y * 128;
    const uint32_t sbase = smem_u32(smem);

    const __nv_bfloat16* Ah = g_Zhi;
    const __nv_bfloat16* Al = g_Zlo;
    const __nv_bfloat16* Bh = g_Whi + layer * 262144;
    const __nv_bfloat16* Bl = g_Wlo + layer * 262144;

    float acc[4][4][4];
    #pragma unroll
    for (int i = 0; i < 4; i++)
        #pragma unroll
        for (int j = 0; j < 4; j++)
            #pragma unroll
            for (int r = 0; r < 4; r++) acc[i][j][r] = 0.f;

    const int lrow = tid >> 1;
    const int lq   = (tid & 1) * 2;

    #define LOAD_STAGE(buf, ks) do { \
        uint32_t dbase = sbase + (uint32_t)((buf) * 4 * MAT_SZ) * 2 + \
                         (uint32_t)(lrow * A_STRIDE + lq * 8) * 2; \
        size_t aoff = (size_t)(m0 + lrow) * 512 + (ks) * 32 + lq * 8; \
        size_t boff = (size_t)(n0 + lrow) * 512 + (ks) * 32 + lq * 8; \
        CPA16(dbase,                    Ah + aoff); \
        CPA16(dbase + 16,               Ah + aoff + 8); \
        CPA16(dbase + MAT_SZ * 2,       Al + aoff); \
        CPA16(dbase + MAT_SZ * 2 + 16,  Al + aoff + 8); \
        CPA16(dbase + MAT_SZ * 4,       Bh + boff); \
        CPA16(dbase + MAT_SZ * 4 + 16,  Bh + boff + 8); \
        CPA16(dbase + MAT_SZ * 6,       Bl + boff); \
        CPA16(dbase + MAT_SZ * 6 + 16,  Bl + boff + 8); \
    } while (0)

    LOAD_STAGE(0, 0);
    CP_COMMIT();

    const int arow = wm * 64 + (lane & 15);
    const int acol = (lane >> 4) * 8;
    const int brow = wn * 32 + (lane & 7) + ((lane >> 4) & 1) * 8;
    const int bcol = ((lane >> 3) & 1) * 8;

    for (int ks = 0; ks < 16; ks++) {
        int buf = ks & 1;
        if (ks + 1 < 16) {
            LOAD_STAGE(buf ^ 1, ks + 1);
            CP_COMMIT();
            CP_WAIT(1);
        } else {
            CP_WAIT(0);
        }
        __syncthreads();

        uint32_t base = sbase + (uint32_t)(buf * 4 * MAT_SZ) * 2;
        #pragma unroll
        for (int sub = 0; sub < 2; sub++) {
            int kb = sub * 16;
            uint32_t ah[4][4], al[4][4], bh[2][4], bl[2][4];
            #pragma unroll
            for (int mt = 0; mt < 4; mt++) {
                LDSM4(ah[mt], base + (uint32_t)((arow + mt * 16) * A_STRIDE + kb + acol) * 2);
                LDSM4(al[mt], base + (uint32_t)(MAT_SZ + (arow + mt * 16) * A_STRIDE + kb + acol) * 2);
            }
            #pragma unroll
            for (int ng = 0; ng < 2; ng++) {
                LDSM4(bh[ng], base + (uint32_t)(2 * MAT_SZ + (brow + ng * 16) * A_STRIDE + kb + bcol) * 2);
                LDSM4(bl[ng], base + (uint32_t)(3 * MAT_SZ + (brow + ng * 16) * A_STRIDE + kb + bcol) * 2);
            }
            #pragma unroll
            for (int mt = 0; mt < 4; mt++) {
                #pragma unroll
                for (int nf = 0; nf < 4; nf++) {
                    const uint32_t* bhf = &bh[nf >> 1][(nf & 1) * 2];
                    const uint32_t* blf = &bl[nf >> 1][(nf & 1) * 2];
                    mma_bf16(acc[mt][nf], ah[mt], bhf);
                    mma_bf16(acc[mt][nf], ah[mt], blf);
                    mma_bf16(acc[mt][nf], al[mt], bhf);
                }
            }
        }
        __syncthreads();
    }

    // ---- fused epilogue: bias + tanh (+residual) -> g_X or g_H ----
    float* dst = dst_is_x ? g_X : g_H;
    float2 bfr[4];
    #pragma unroll
    for (int nf = 0; nf < 4; nf++) {
        int col = n0 + wn * 32 + nf * 8 + (lane & 3) * 2;
        bfr[nf] = *(const float2*)&bias[col];
    }
    #pragma unroll
    for (int mt = 0; mt < 4; mt++) {
        int row = m0 + wm * 64 + mt * 16 + (lane >> 2);
        #pragma unroll
        for (int nf = 0; nf < 4; nf++) {
            int col = n0 + wn * 32 + nf * 8 + (lane & 3) * 2;
            size_t i0 = (size_t)row * 512 + col;
            size_t i1 = (size_t)(row + 8) * 512 + col;
            float v0 = tanhf(acc[mt][nf][0] + bfr[nf].x);
            float v1 = tanhf(acc[mt][nf][1] + bfr[nf].y);
            float v2 = tanhf(acc[mt][nf][2] + bfr[nf].x);
            float v3 = tanhf(acc[mt][nf][3] + bfr[nf].y);
            if (residual) {
                float2 o0 = *(const float2*)&g_X[i0];
                float2 o1 = *(const float2*)&g_X[i1];
                v0 += o0.x; v1 += o0.y; v2 += o1.x; v3 += o1.y;
            }
            *(float2*)&dst[i0] = make_float2(v0, v1);
            *(float2*)&dst[i1] = make_float2(v2, v3);
        }
    }
}

// ======================= tail: gc7 + fused + MLP ===========================
#define TAIL_SMEM ((480 + 480 + 480 + 5120 + 1920 + 12288) * 4)
__global__ void __launch_bounds__(512)
tail_kernel(const float* __restrict__ gc7_w, const float* __restrict__ gc7_att,
            const float* __restrict__ gc7_b, const float* __restrict__ mlp_w1,
            const float* __restrict__ mlp_w2, float* __restrict__ out) {
    extern __shared__ float sm[];
    float* sDct = sm;
    float* sP   = sDct + 480;
    float* sOut = sP + 480;
    float* sW7  = sOut + 480;      // [o][k] 10x512
    float* sFused = sW7 + 5120;    // 48x40
    float* sH   = sFused + 1920;   // 48x256
    const int tid = threadIdx.x, b = blockIdx.x;

    if (tid < 480) sDct[tid] = g_dct[b * 480 + tid];
    for (int i = tid; i < 5120; i += 512) {
        int o = i / 512, k = i % 512;
        sW7[o * 512 + k] = __ldg(gc7_w + k * 10 + o);
    }
    __syncthreads();
    if (tid < 480) {
        int m = tid / 10, o = tid % 10;
        const float* yr = g_X + (size_t)(b * 48 + m) * 512;
        const float* wr = sW7 + o * 512;
        float a0=0,a1=0,a2=0,a3=0;
        for (int k = 0; k < 512; k += 4) {
            float4 y4 = *(const float4*)(yr + k);
            float4 w4 = *(const float4*)(wr + k);
            a0 += y4.x*w4.x; a1 += y4.y*w4.y; a2 += y4.z*w4.z; a3 += y4.w*w4.w;
        }
        sP[tid] = a0 + a1 + a2 + a3;
    }
    __syncthreads();
    if (tid < 480) {
        int n = tid / 10, o = tid % 10;
        float a = __ldg(gc7_b + o) + sDct[tid];
        for (int m = 0; m < 48; m++) a += __ldg(gc7_att + n * 48 + m) * sP[m * 10 + o];
        sOut[tid] = a;
    }
    __syncthreads();
    for (int i = tid; i < 1920; i += 512) {
        int f = i % 48, t = i / 48;
        float v;
        if (t < 30) {
            v = 0.f;
            #pragma unroll
            for (int d = 0; d < 10; d++) {
                float wd = (d == 0) ? W0_DCT : W1_DCT;
                v += wd * cosf(PI_F * ((float)t + 0.5f) * (float)d / 30.0f)
                        * sOut[f * 10 + d];
            }
        } else v = g_ffc[b * 480 + f * 10 + (t - 30)];
        sFused[f * 40 + t] = v;
    }
    __syncthreads();
    {
        int o = tid & 255, fg = tid >> 8;
        float w1r[40];
        #pragma unroll
        for (int t = 0; t < 40; t++) w1r[t] = __ldg(mlp_w1 + o * 40 + t);
        for (int f = fg * 24; f < fg * 24 + 24; f++) {
            float a = 0.f;
            #pragma unroll
            for (int t = 0; t < 40; t++) a += w1r[t] * sFused[f * 40 + t];
            sH[f * 256 + o] = (a > 0.f) ? a : 0.f;
        }
    }
    __syncthreads();
    if (tid < 480) {
        int f = tid / 10, t2 = tid % 10;
        float a0=0,a1=0,a2=0,a3=0;
        const float* hr = sH + f * 256;
        const float* w2 = mlp_w2 + t2 * 256;
        for (int o = 0; o < 256; o += 4) {
            a0 += hr[o]*__ldg(w2+o);     a1 += hr[o+1]*__ldg(w2+o+1);
            a2 += hr[o+2]*__ldg(w2+o+2); a3 += hr[o+3]*__ldg(w2+o+3);
        }
        out[b * 480 + t2 * 48 + f] = a0 + a1 + a2 + a3;
    }
}

// ===========================================================================
extern "C" void kernel_launch(void* const* d_in, const int* in_sizes, int n_in,
                              void* d_out, int out_size) {
    const float* seq     = (const float*)d_in[0];
    const float* gc1_w   = (const float*)d_in[5];
    const float* gc1_att = (const float*)d_in[6];
    const float* gc1_b   = (const float*)d_in[7];
    const float* gcb_w   = (const float*)d_in[8];
    const float* gcb_att = (const float*)d_in[9];
    const float* gcb_b   = (const float*)d_in[10];
    const float* gc7_w   = (const float*)d_in[11];
    const float* gc7_att = (const float*)d_in[12];
    const float* gc7_b   = (const float*)d_in[13];
    const float* mlp_w1  = (const float*)d_in[14];
    const float* mlp_w2  = (const float*)d_in[15];
    const float* ffc_wl  = (const float*)d_in[16];
    const float* ffc_wg  = (const float*)d_in[17];
    float* out = (float*)d_out;

    int B = in_sizes[0] / 2400;           // 1024
    int gm = (B * 48) / 128;              // 384 m-tiles

    cudaFuncSetAttribute(gemm_kernel,
        cudaFuncAttributeMaxDynamicSharedMemorySize, GEMM_SMEM);
    cudaFuncSetAttribute(tail_kernel,
        cudaFuncAttributeMaxDynamicSharedMemorySize, TAIL_SMEM);

    prep_w_kernel<<<4096, 256>>>(gcb_w);
    ffc_kernel<<<B * 16, 64>>>(seq, ffc_wl, ffc_wg);
    gc1_kernel<<<B, 512>>>(seq, gc1_w, gc1_att, gc1_b);

    for (int l = 0; l < 4; l++) {
        // l=0: Z=att@y0 (g_X) -> h1 = tanh(...) -> g_H
        // l=1: Z=att@h1 (g_H) -> y1 = y0 + tanh(...) -> g_X
        // l=2: Z=att@y1 (g_X) -> h2 -> g_H
        // l=3: Z=att@h2 (g_H) -> y2 = y1 + tanh(...) -> g_X
        att_z_kernel<<<B, 512>>>(gcb_att + l * 2304, (l & 1) == 0);
        gemm_kernel<<<dim3(4, gm), 256, GEMM_SMEM>>>(l, l & 1, l & 1,
                                                     gcb_b + l * 512);
    }
    tail_kernel<<<B, 512, TAIL_SMEM>>>(gc7_w, gc7_att, gc7_b,
                                       mlp_w1, mlp_w2, out);
}

// round 9
// speedup vs baseline: 1.1788x; 1.1788x over previous
#include <cuda_runtime.h>
#include <cuda_bf16.h>
#include <math.h>
#include <cstdint>

// ---------------------------------------------------------------------------
// DAFCN forward, B=1024, T=50, F=48, D=512.
// Attention branch (wq*/wk*, dvb, attended) dead: combined[:,:,:10] = gcn_out.
// R9: gemm m-tile = 96 rows = 2 whole batches; att@G + bias + tanh (+residual)
//     fused into the GEMM epilogue via SMEM (G never hits gmem). 2 CTAs/SM.
//     Per layer ONE kernel: Y = [residual +] tanh(att @ (X@W) + b).
// ---------------------------------------------------------------------------

typedef unsigned long long ull;

#define PI_F 3.14159265358979f
#define W0_DCT 0.18257418583505537f
#define W1_DCT 0.2581988897471611f
#define NB 1024
#define MROWS (NB * 48)

__device__ float         g_X[MROWS * 512];      // fp32 y (residual carrier)
__device__ __nv_bfloat16 g_Ahi[MROWS * 512];    // gemm A operand hi (y or h)
__device__ __nv_bfloat16 g_Alo[MROWS * 512];    // gemm A operand lo
__device__ __nv_bfloat16 g_Whi[4 * 512 * 512];  // W^T [l][n][k] hi
__device__ __nv_bfloat16 g_Wlo[4 * 512 * 512];  // W^T [l][n][k] lo
__device__ float         g_dct[NB * 480];
__device__ float         g_ffc[NB * 480];

// ---- packed f32x2 helpers -------------------------------------------------
__device__ __forceinline__ ull pk2(float lo, float hi) {
    ull r; asm("mov.b64 %0, {%1, %2};" : "=l"(r) : "f"(lo), "f"(hi)); return r;
}
__device__ __forceinline__ void fma2f(ull &d, ull a, ull b) {
    asm("fma.rn.f32x2 %0, %1, %2, %0;" : "+l"(d) : "l"(a), "l"(b));
}
__device__ __forceinline__ float2 up2(ull v) {
    float lo, hi; asm("mov.b64 {%0, %1}, %2;" : "=f"(lo), "=f"(hi) : "l"(v));
    return make_float2(lo, hi);
}
__device__ __forceinline__ uint32_t smem_u32(const void* p) {
    uint32_t a;
    asm("{ .reg .u64 t; cvta.to.shared.u64 t, %1; cvt.u32.u64 %0, t; }"
        : "=r"(a) : "l"(p));
    return a;
}

#define CPA16(dst, src) \
    asm volatile("cp.async.cg.shared.global [%0], [%1], 16;" \
                 :: "r"(dst), "l"(src))
#define CP_COMMIT() asm volatile("cp.async.commit_group;" ::: "memory")
#define CP_WAIT(n)  asm volatile("cp.async.wait_group %0;" :: "n"(n) : "memory")

#define LDSM4(r, addr) \
    asm volatile("ldmatrix.sync.aligned.m8n8.x4.shared.b16 {%0,%1,%2,%3}, [%4];" \
        : "=r"((r)[0]), "=r"((r)[1]), "=r"((r)[2]), "=r"((r)[3]) : "r"(addr))

__device__ __forceinline__ void mma_bf16(float* d, const uint32_t* a,
                                         const uint32_t* b) {
    asm volatile(
        "mma.sync.aligned.m16n8k16.row.col.f32.bf16.bf16.f32 "
        "{%0,%1,%2,%3}, {%4,%5,%6,%7}, {%8,%9}, {%0,%1,%2,%3};"
        : "+f"(d[0]), "+f"(d[1]), "+f"(d[2]), "+f"(d[3])
        : "r"(a[0]), "r"(a[1]), "r"(a[2]), "r"(a[3]), "r"(b[0]), "r"(b[1]));
}

// ======================= prep_w: W^T bf16 hi/lo ============================
__global__ void prep_w_kernel(const float* __restrict__ gcb_w) {
    int idx = blockIdx.x * 256 + threadIdx.x;      // 4*512*512
    int l = idx >> 18, k = (idx >> 9) & 511, n = idx & 511;
    float w = gcb_w[l * 262144 + k * 512 + n];
    __nv_bfloat16 hi = __float2bfloat16(w);
    __nv_bfloat16 lo = __float2bfloat16(w - __bfloat162float(hi));
    int dst = l * 262144 + n * 512 + k;
    g_Whi[dst] = hi; g_Wlo[dst] = lo;
}

// ======================= FFC ===============================================
__global__ void ffc_kernel(const float* __restrict__ seq,
                           const float* __restrict__ wl,
                           const float* __restrict__ wg) {
    int bx = blockIdx.x, b = bx >> 4, g = bx & 15, tid = threadIdx.x;
    __shared__ float sXf[3][60], sV[6][31], sc[60], ss[60], sWg[36], sWl[9];
    if (tid < 60) {
        float a = 6.283185307179586f * (float)tid / 60.0f;
        sc[tid] = cosf(a); ss[tid] = sinf(a);
    }
    if (tid < 36) sWg[tid] = wg[tid];
    if (tid < 9)  sWl[tid] = wl[tid];
    for (int i = tid; i < 180; i += 64) {
        int c = i / 60, t = i % 60, tsrc = (t < 50) ? t : 49;
        sXf[c][t] = seq[b * 2400 + tsrc * 48 + c * 16 + g];
    }
    __syncthreads();
    if (tid < 31) {
        int k = tid;
        float re0=0,re1=0,re2=0,im0=0,im1=0,im2=0; int idx = 0;
        for (int t = 0; t < 60; t++) {
            float co = sc[idx], si = ss[idx];
            float x0 = sXf[0][t], x1 = sXf[1][t], x2 = sXf[2][t];
            re0 += x0*co; im0 -= x0*si; re1 += x1*co; im1 -= x1*si;
            re2 += x2*co; im2 -= x2*si;
            idx += k; if (idx >= 60) idx -= 60;
        }
        float U[6] = {re0, re1, re2, im0, im1, im2};
        #pragma unroll
        for (int o = 0; o < 6; o++) {
            float a = 0.f;
            #pragma unroll
            for (int c = 0; c < 6; c++) a += sWg[o * 6 + c] * U[c];
            sV[o][k] = (a > 0.f) ? a : 0.f;
        }
    }
    __syncthreads();
    if (tid < 30) {
        int o = tid / 10, t = tid % 10;
        float spec = sV[o][0] + ((t & 1) ? -sV[o][30] : sV[o][30]);
        int idx = t;
        for (int k = 1; k < 30; k++) {
            spec += 2.0f * (sV[o][k] * sc[idx] - sV[o + 3][k] * ss[idx]);
            idx += t; if (idx >= 60) idx -= 60;
        }
        float v = spec * (1.0f / 60.0f);
        #pragma unroll
        for (int c = 0; c < 3; c++) v += sWl[o * 3 + c] * sXf[c][t];
        g_ffc[b * 480 + (o * 16 + g) * 10 + t] = v;
    }
}

// ======================= gc1 head: y0 -> g_X + bf16 emit ===================
__global__ void __launch_bounds__(512)
gc1_kernel(const float* __restrict__ seq, const float* __restrict__ gc1_w,
           const float* __restrict__ gc1_att, const float* __restrict__ gc1_b) {
    __shared__ float sDct[480], sZ1[480];
    const int tid = threadIdx.x, b = blockIdx.x;
    const float* sq = seq + b * 2400;
    if (tid < 480) {
        int f = tid % 48, d = tid / 48;
        float wd = (d == 0) ? W0_DCT : W1_DCT;
        float acc = 0.f, Sd = 0.f;
        for (int k = 0; k < 30; k++) {
            float cv = wd * cosf(PI_F * ((float)k + 0.5f) * (float)d / 30.0f);
            if (k < 10) acc += cv * sq[(40 + k) * 48 + f];
            else        Sd  += cv;
        }
        acc += Sd * sq[49 * 48 + f];
        sDct[f * 10 + d] = acc;
        g_dct[b * 480 + f * 10 + d] = acc;
    }
    __syncthreads();
    if (tid < 480) {
        int n = tid / 10, d = tid % 10;
        float a = 0.f;
        for (int m = 0; m < 48; m++) a += __ldg(gc1_att + n * 48 + m) * sDct[m * 10 + d];
        sZ1[n * 10 + d] = a;
    }
    __syncthreads();
    float w10[10];
    #pragma unroll
    for (int d = 0; d < 10; d++) w10[d] = __ldg(gc1_w + d * 512 + tid);
    float bb = __ldg(gc1_b + tid);
    for (int n = 0; n < 48; n++) {
        float a = bb;
        #pragma unroll
        for (int d = 0; d < 10; d++) a += w10[d] * sZ1[n * 10 + d];
        float v = tanhf(a);
        size_t idx = (size_t)(b * 48 + n) * 512 + tid;
        g_X[idx] = v;
        __nv_bfloat16 hi = __float2bfloat16(v);
        g_Ahi[idx] = hi;
        g_Alo[idx] = __float2bfloat16(v - __bfloat162float(hi));
    }
}

// ===========================================================================
// Fused layer kernel: bf16x3 HMMA mainloop (m-tile 96 = 2 batches, n-tile 128)
// + in-SMEM epilogue: Y = [g_X +] tanh(att @ G + bias), emit bf16 hi/lo.
// 8 warps: wm in {0,1} (48 rows), wn in {0..3} (32 cols).
// ===========================================================================
#define ASTR 40                      // bf16 per SMEM row (32 data + 8 pad)
#define STG_A  (96  * ASTR * 2)      // 7680 B per A matrix
#define STG_B  (128 * ASTR * 2)      // 10240 B per B matrix
#define STG_SZ (2 * STG_A + 2 * STG_B)  // 35840 B per stage
#define GEMM_SMEM (2 * STG_SZ)       // 71680 B

__global__ void __launch_bounds__(256, 2)
layer_kernel(int layer, int residual, int emit,
             const float* __restrict__ att, const float* __restrict__ bias) {
    extern __shared__ __align__(16) char smem[];
    const int tid = threadIdx.x;
    const int lane = tid & 31, wid = tid >> 5;
    const int wm = wid >> 2, wn = wid & 3;
    const int n0 = blockIdx.x * 128;
    const int m0 = blockIdx.y * 96;           // 2 batches
    const uint32_t sbase = smem_u32(smem);

    const __nv_bfloat16* Ah = g_Ahi;
    const __nv_bfloat16* Al = g_Alo;
    const __nv_bfloat16* Bh = g_Whi + layer * 262144;
    const __nv_bfloat16* Bl = g_Wlo + layer * 262144;

    float acc[3][4][4];
    #pragma unroll
    for (int i = 0; i < 3; i++)
        #pragma unroll
        for (int j = 0; j < 4; j++)
            #pragma unroll
            for (int r = 0; r < 4; r++) acc[i][j][r] = 0.f;

    // ---- stage loader: 448 rows x 64B = 1792 16B-chunks = 7 per thread ----
    #define LOAD_STAGE(buf, ks) do { \
        uint32_t stg = sbase + (buf) * STG_SZ; \
        _Pragma("unroll") \
        for (int it = 0; it < 7; it++) { \
            int i = it * 256 + tid; \
            int r = i >> 2, q = i & 3; \
            uint32_t dst; const __nv_bfloat16* src; \
            if (r < 96) { \
                dst = stg + r * 80 + q * 16; \
                src = Ah + (size_t)(m0 + r) * 512 + (ks) * 32 + q * 8; \
            } else if (r < 192) { \
                dst = stg + STG_A + (r - 96) * 80 + q * 16; \
                src = Al + (size_t)(m0 + r - 96) * 512 + (ks) * 32 + q * 8; \
            } else if (r < 320) { \
                dst = stg + 2 * STG_A + (r - 192) * 80 + q * 16; \
                src = Bh + (size_t)(n0 + r - 192) * 512 + (ks) * 32 + q * 8; \
            } else { \
                dst = stg + 2 * STG_A + STG_B + (r - 320) * 80 + q * 16; \
                src = Bl + (size_t)(n0 + r - 320) * 512 + (ks) * 32 + q * 8; \
            } \
            CPA16(dst, src); \
        } \
    } while (0)

    LOAD_STAGE(0, 0);
    CP_COMMIT();

    const int arow = wm * 48 + (lane & 15);
    const int acol = (lane >> 4) * 8;
    const int brow = wn * 32 + (lane & 7) + ((lane >> 4) & 1) * 8;
    const int bcol = ((lane >> 3) & 1) * 8;

    for (int ks = 0; ks < 16; ks++) {
        int buf = ks & 1;
        if (ks + 1 < 16) {
            LOAD_STAGE(buf ^ 1, ks + 1);
            CP_COMMIT();
            CP_WAIT(1);
        } else {
            CP_WAIT(0);
        }
        __syncthreads();

        uint32_t base = sbase + buf * STG_SZ;
        #pragma unroll
        for (int sub = 0; sub < 2; sub++) {
            int kb = sub * 16;
            uint32_t ah[3][4], al[3][4], bh[2][4], bl[2][4];
            #pragma unroll
            for (int mt = 0; mt < 3; mt++) {
                LDSM4(ah[mt], base + (uint32_t)((arow + mt * 16) * ASTR + kb + acol) * 2);
                LDSM4(al[mt], base + STG_A + (uint32_t)((arow + mt * 16) * ASTR + kb + acol) * 2);
            }
            #pragma unroll
            for (int ng = 0; ng < 2; ng++) {
                LDSM4(bh[ng], base + 2 * STG_A + (uint32_t)((brow + ng * 16) * ASTR + kb + bcol) * 2);
                LDSM4(bl[ng], base + 2 * STG_A + STG_B + (uint32_t)((brow + ng * 16) * ASTR + kb + bcol) * 2);
            }
            #pragma unroll
            for (int mt = 0; mt < 3; mt++) {
                #pragma unroll
                for (int nf = 0; nf < 4; nf++) {
                    const uint32_t* bhf = &bh[nf >> 1][(nf & 1) * 2];
                    const uint32_t* blf = &bl[nf >> 1][(nf & 1) * 2];
                    mma_bf16(acc[mt][nf], ah[mt], bhf);
                    mma_bf16(acc[mt][nf], ah[mt], blf);
                    mma_bf16(acc[mt][nf], al[mt], bhf);
                }
            }
        }
        __syncthreads();
    }

    // ================= fused epilogue: att @ G + bias + tanh ===============
    // sG [96][132] fp32, sAttT [48][48] fp32 (attT[m][n] = att[n][m]).
    float* sG = (float*)smem;                 // 96*132*4 = 50688 B
    float* sAttT = sG + 96 * 132;             // + 9216 B = 59904 <= 71680

    #pragma unroll
    for (int mt = 0; mt < 3; mt++) {
        int row = wm * 48 + mt * 16 + (lane >> 2);
        #pragma unroll
        for (int nf = 0; nf < 4; nf++) {
            int col = wn * 32 + nf * 8 + (lane & 3) * 2;
            sG[row * 132 + col]           = acc[mt][nf][0];
            sG[row * 132 + col + 1]       = acc[mt][nf][1];
            sG[(row + 8) * 132 + col]     = acc[mt][nf][2];
            sG[(row + 8) * 132 + col + 1] = acc[mt][nf][3];
        }
    }
    for (int i = tid; i < 2304; i += 256) {
        int m = i / 48, n = i % 48;
        sAttT[m * 48 + n] = __ldg(att + n * 48 + m);
    }
    __syncthreads();

    {
        const int lc = tid & 127;             // local col 0..127
        const int b2 = tid >> 7;              // local batch 0/1
        float g[48];
        #pragma unroll
        for (int m = 0; m < 48; m++) g[m] = sG[(b2 * 48 + m) * 132 + lc];

        ull gacc[24];
        #pragma unroll
        for (int j = 0; j < 24; j++) gacc[j] = 0ull;
        #pragma unroll 4
        for (int m = 0; m < 48; m++) {
            ull gp = pk2(g[m], g[m]);
            const ull* ap = (const ull*)(sAttT + m * 48);
            #pragma unroll
            for (int j = 0; j < 24; j++) fma2f(gacc[j], ap[j], gp);
        }

        const int col = n0 + lc;
        const float bb = __ldg(bias + col);
        const size_t rowbase = (size_t)(m0 + b2 * 48) * 512 + col;
        #pragma unroll
        for (int j = 0; j < 24; j++) {
            float2 z = up2(gacc[j]);
            float v0 = tanhf(z.x + bb);
            float v1 = tanhf(z.y + bb);
            size_t i0 = rowbase + (size_t)(2 * j) * 512;
            size_t i1 = i0 + 512;
            if (residual) {
                v0 += g_X[i0];
                v1 += g_X[i1];
                g_X[i0] = v0;
                g_X[i1] = v1;
            }
            if (emit) {
                __nv_bfloat16 h0 = __float2bfloat16(v0);
                __nv_bfloat16 h1 = __float2bfloat16(v1);
                g_Ahi[i0] = h0;
                g_Alo[i0] = __float2bfloat16(v0 - __bfloat162float(h0));
                g_Ahi[i1] = h1;
                g_Alo[i1] = __float2bfloat16(v1 - __bfloat162float(h1));
            }
        }
    }
}

// ======================= tail: gc7 + fused + MLP ===========================
#define TAIL_SMEM ((480 + 480 + 480 + 5120 + 1920 + 12288) * 4)
__global__ void __launch_bounds__(512)
tail_kernel(const float* __restrict__ gc7_w, const float* __restrict__ gc7_att,
            const float* __restrict__ gc7_b, const float* __restrict__ mlp_w1,
            const float* __restrict__ mlp_w2, float* __restrict__ out) {
    extern __shared__ float sm[];
    float* sDct = sm;
    float* sP   = sDct + 480;
    float* sOut = sP + 480;
    float* sW7  = sOut + 480;      // [o][k] 10x512
    float* sFused = sW7 + 5120;    // 48x40
    float* sH   = sFused + 1920;   // 48x256
    const int tid = threadIdx.x, b = blockIdx.x;

    if (tid < 480) sDct[tid] = g_dct[b * 480 + tid];
    for (int i = tid; i < 5120; i += 512) {
        int o = i / 512, k = i % 512;
        sW7[o * 512 + k] = __ldg(gc7_w + k * 10 + o);
    }
    __syncthreads();
    if (tid < 480) {
        int m = tid / 10, o = tid % 10;
        const float* yr = g_X + (size_t)(b * 48 + m) * 512;
        const float* wr = sW7 + o * 512;
        float a0=0,a1=0,a2=0,a3=0;
        for (int k = 0; k < 512; k += 4) {
            float4 y4 = *(const float4*)(yr + k);
            float4 w4 = *(const float4*)(wr + k);
            a0 += y4.x*w4.x; a1 += y4.y*w4.y; a2 += y4.z*w4.z; a3 += y4.w*w4.w;
        }
        sP[tid] = a0 + a1 + a2 + a3;
    }
    __syncthreads();
    if (tid < 480) {
        int n = tid / 10, o = tid % 10;
        float a = __ldg(gc7_b + o) + sDct[tid];
        for (int m = 0; m < 48; m++) a += __ldg(gc7_att + n * 48 + m) * sP[m * 10 + o];
        sOut[tid] = a;
    }
    __syncthreads();
    for (int i = tid; i < 1920; i += 512) {
        int f = i % 48, t = i / 48;
        float v;
        if (t < 30) {
            v = 0.f;
            #pragma unroll
            for (int d = 0; d < 10; d++) {
                float wd = (d == 0) ? W0_DCT : W1_DCT;
                v += wd * cosf(PI_F * ((float)t + 0.5f) * (float)d / 30.0f)
                        * sOut[f * 10 + d];
            }
        } else v = g_ffc[b * 480 + f * 10 + (t - 30)];
        sFused[f * 40 + t] = v;
    }
    __syncthreads();
    {
        int o = tid & 255, fg = tid >> 8;
        float w1r[40];
        #pragma unroll
        for (int t = 0; t < 40; t++) w1r[t] = __ldg(mlp_w1 + o * 40 + t);
        for (int f = fg * 24; f < fg * 24 + 24; f++) {
            float a = 0.f;
            #pragma unroll
            for (int t = 0; t < 40; t++) a += w1r[t] * sFused[f * 40 + t];
            sH[f * 256 + o] = (a > 0.f) ? a : 0.f;
        }
    }
    __syncthreads();
    if (tid < 480) {
        int f = tid / 10, t2 = tid % 10;
        float a0=0,a1=0,a2=0,a3=0;
        const float* hr = sH + f * 256;
        const float* w2 = mlp_w2 + t2 * 256;
        for (int o = 0; o < 256; o += 4) {
            a0 += hr[o]*__ldg(w2+o);     a1 += hr[o+1]*__ldg(w2+o+1);
            a2 += hr[o+2]*__ldg(w2+o+2); a3 += hr[o+3]*__ldg(w2+o+3);
        }
        out[b * 480 + t2 * 48 + f] = a0 + a1 + a2 + a3;
    }
}

// ===========================================================================
extern "C" void kernel_launch(void* const* d_in, const int* in_sizes, int n_in,
                              void* d_out, int out_size) {
    const float* seq     = (const float*)d_in[0];
    const float* gc1_w   = (const float*)d_in[5];
    const float* gc1_att = (const float*)d_in[6];
    const float* gc1_b   = (const float*)d_in[7];
    const float* gcb_w   = (const float*)d_in[8];
    const float* gcb_att = (const float*)d_in[9];
    const float* gcb_b   = (const float*)d_in[10];
    const float* gc7_w   = (const float*)d_in[11];
    const float* gc7_att = (const float*)d_in[12];
    const float* gc7_b   = (const float*)d_in[13];
    const float* mlp_w1  = (const float*)d_in[14];
    const float* mlp_w2  = (const float*)d_in[15];
    const float* ffc_wl  = (const float*)d_in[16];
    const float* ffc_wg  = (const float*)d_in[17];
    float* out = (float*)d_out;

    int B = in_sizes[0] / 2400;           // 1024
    int gm = (B * 48) / 96;               // 512 m-tiles (2 batches each)

    cudaFuncSetAttribute(layer_kernel,
        cudaFuncAttributeMaxDynamicSharedMemorySize, GEMM_SMEM);
    cudaFuncSetAttribute(tail_kernel,
        cudaFuncAttributeMaxDynamicSharedMemorySize, TAIL_SMEM);

    prep_w_kernel<<<4096, 256>>>(gcb_w);
    ffc_kernel<<<B * 16, 64>>>(seq, ffc_wl, ffc_wg);
    gc1_kernel<<<B, 512>>>(seq, gc1_w, gc1_att, gc1_b);

    for (int l = 0; l < 4; l++) {
        // l even: h = tanh(att@(A@W)+b), emit bf16 only (fp32 h never needed)
        // l odd : y += tanh(att@(A@W)+b) in g_X, emit bf16 (except l=3)
        layer_kernel<<<dim3(4, gm), 256, GEMM_SMEM>>>(
            l, l & 1, (l < 3) ? 1 : 0,
            gcb_att + l * 2304, gcb_b + l * 512);
    }
    tail_kernel<<<B, 512, TAIL_SMEM>>>(gc7_w, gc7_att, gc7_b,
                                       mlp_w1, mlp_w2, out);
}

// round 10
// speedup vs baseline: 1.4111x; 1.1971x over previous
#include <cuda_runtime.h>
#include <cuda_fp16.h>
#include <math.h>
#include <cstdint>

// ---------------------------------------------------------------------------
// DAFCN forward, B=1024, T=50, F=48, D=512.
// Attention branch (wq*/wk*, dvb, attended) dead: combined[:,:,:10] = gcn_out.
// R10: fp16x2 GEMM (A in plain fp16, W split fp16 hi/lo -> 2 MMA passes vs 3),
//      fused att+bias+tanh epilogue (R9), fast tanh via __expf.
// ---------------------------------------------------------------------------

typedef unsigned long long ull;

#define PI_F 3.14159265358979f
#define W0_DCT 0.18257418583505537f
#define W1_DCT 0.2581988897471611f
#define NB 1024
#define MROWS (NB * 48)

__device__ float  g_X[MROWS * 512];       // fp32 y (residual carrier)
__device__ __half g_Af[MROWS * 512];      // fp16 gemm A operand (y or h)
__device__ __half g_Wh[4 * 512 * 512];    // W^T [l][n][k] fp16 hi
__device__ __half g_Wl[4 * 512 * 512];    // W^T [l][n][k] fp16 lo
__device__ float  g_dct[NB * 480];
__device__ float  g_ffc[NB * 480];

// ---- helpers --------------------------------------------------------------
__device__ __forceinline__ ull pk2(float lo, float hi) {
    ull r; asm("mov.b64 %0, {%1, %2};" : "=l"(r) : "f"(lo), "f"(hi)); return r;
}
__device__ __forceinline__ void fma2f(ull &d, ull a, ull b) {
    asm("fma.rn.f32x2 %0, %1, %2, %0;" : "+l"(d) : "l"(a), "l"(b));
}
__device__ __forceinline__ float2 up2(ull v) {
    float lo, hi; asm("mov.b64 {%0, %1}, %2;" : "=f"(lo), "=f"(hi) : "l"(v));
    return make_float2(lo, hi);
}
__device__ __forceinline__ uint32_t smem_u32(const void* p) {
    uint32_t a;
    asm("{ .reg .u64 t; cvta.to.shared.u64 t, %1; cvt.u32.u64 %0, t; }"
        : "=r"(a) : "l"(p));
    return a;
}
// fast tanh: abs err ~1e-7, saturates correctly at +/-inf (no NaN)
__device__ __forceinline__ float ftanh(float x) {
    return 1.0f - __fdividef(2.0f, __expf(2.0f * x) + 1.0f);
}

#define CPA16(dst, src) \
    asm volatile("cp.async.cg.shared.global [%0], [%1], 16;" \
                 :: "r"(dst), "l"(src))
#define CP_COMMIT() asm volatile("cp.async.commit_group;" ::: "memory")
#define CP_WAIT(n)  asm volatile("cp.async.wait_group %0;" :: "n"(n) : "memory")

#define LDSM4(r, addr) \
    asm volatile("ldmatrix.sync.aligned.m8n8.x4.shared.b16 {%0,%1,%2,%3}, [%4];" \
        : "=r"((r)[0]), "=r"((r)[1]), "=r"((r)[2]), "=r"((r)[3]) : "r"(addr))

__device__ __forceinline__ void mma_f16(float* d, const uint32_t* a,
                                        const uint32_t* b) {
    asm volatile(
        "mma.sync.aligned.m16n8k16.row.col.f32.f16.f16.f32 "
        "{%0,%1,%2,%3}, {%4,%5,%6,%7}, {%8,%9}, {%0,%1,%2,%3};"
        : "+f"(d[0]), "+f"(d[1]), "+f"(d[2]), "+f"(d[3])
        : "r"(a[0]), "r"(a[1]), "r"(a[2]), "r"(a[3]), "r"(b[0]), "r"(b[1]));
}

// ======================= prep_w: W^T fp16 hi/lo ============================
__global__ void prep_w_kernel(const float* __restrict__ gcb_w) {
    int idx = blockIdx.x * 256 + threadIdx.x;      // 4*512*512
    int l = idx >> 18, k = (idx >> 9) & 511, n = idx & 511;
    float w = gcb_w[l * 262144 + k * 512 + n];
    __half hi = __float2half_rn(w);
    __half lo = __float2half_rn(w - __half2float(hi));
    int dst = l * 262144 + n * 512 + k;
    g_Wh[dst] = hi; g_Wl[dst] = lo;
}

// ======================= FFC ===============================================
__global__ void ffc_kernel(const float* __restrict__ seq,
                           const float* __restrict__ wl,
                           const float* __restrict__ wg) {
    int bx = blockIdx.x, b = bx >> 4, g = bx & 15, tid = threadIdx.x;
    __shared__ float sXf[3][60], sV[6][31], sc[60], ss[60], sWg[36], sWl[9];
    if (tid < 60) {
        float a = 6.283185307179586f * (float)tid / 60.0f;
        sc[tid] = cosf(a); ss[tid] = sinf(a);
    }
    if (tid < 36) sWg[tid] = wg[tid];
    if (tid < 9)  sWl[tid] = wl[tid];
    for (int i = tid; i < 180; i += 64) {
        int c = i / 60, t = i % 60, tsrc = (t < 50) ? t : 49;
        sXf[c][t] = seq[b * 2400 + tsrc * 48 + c * 16 + g];
    }
    __syncthreads();
    if (tid < 31) {
        int k = tid;
        float re0=0,re1=0,re2=0,im0=0,im1=0,im2=0; int idx = 0;
        for (int t = 0; t < 60; t++) {
            float co = sc[idx], si = ss[idx];
            float x0 = sXf[0][t], x1 = sXf[1][t], x2 = sXf[2][t];
            re0 += x0*co; im0 -= x0*si; re1 += x1*co; im1 -= x1*si;
            re2 += x2*co; im2 -= x2*si;
            idx += k; if (idx >= 60) idx -= 60;
        }
        float U[6] = {re0, re1, re2, im0, im1, im2};
        #pragma unroll
        for (int o = 0; o < 6; o++) {
            float a = 0.f;
            #pragma unroll
            for (int c = 0; c < 6; c++) a += sWg[o * 6 + c] * U[c];
            sV[o][k] = (a > 0.f) ? a : 0.f;
        }
    }
    __syncthreads();
    if (tid < 30) {
        int o = tid / 10, t = tid % 10;
        float spec = sV[o][0] + ((t & 1) ? -sV[o][30] : sV[o][30]);
        int idx = t;
        for (int k = 1; k < 30; k++) {
            spec += 2.0f * (sV[o][k] * sc[idx] - sV[o + 3][k] * ss[idx]);
            idx += t; if (idx >= 60) idx -= 60;
        }
        float v = spec * (1.0f / 60.0f);
        #pragma unroll
        for (int c = 0; c < 3; c++) v += sWl[o * 3 + c] * sXf[c][t];
        g_ffc[b * 480 + (o * 16 + g) * 10 + t] = v;
    }
}

// ======================= gc1 head: y0 -> g_X + fp16 emit ===================
__global__ void __launch_bounds__(512)
gc1_kernel(const float* __restrict__ seq, const float* __restrict__ gc1_w,
           const float* __restrict__ gc1_att, const float* __restrict__ gc1_b) {
    __shared__ float sDct[480], sZ1[480];
    const int tid = threadIdx.x, b = blockIdx.x;
    const float* sq = seq + b * 2400;
    if (tid < 480) {
        int f = tid % 48, d = tid / 48;
        float wd = (d == 0) ? W0_DCT : W1_DCT;
        float acc = 0.f, Sd = 0.f;
        for (int k = 0; k < 30; k++) {
            float cv = wd * cosf(PI_F * ((float)k + 0.5f) * (float)d / 30.0f);
            if (k < 10) acc += cv * sq[(40 + k) * 48 + f];
            else        Sd  += cv;
        }
        acc += Sd * sq[49 * 48 + f];
        sDct[f * 10 + d] = acc;
        g_dct[b * 480 + f * 10 + d] = acc;
    }
    __syncthreads();
    if (tid < 480) {
        int n = tid / 10, d = tid % 10;
        float a = 0.f;
        for (int m = 0; m < 48; m++) a += __ldg(gc1_att + n * 48 + m) * sDct[m * 10 + d];
        sZ1[n * 10 + d] = a;
    }
    __syncthreads();
    float w10[10];
    #pragma unroll
    for (int d = 0; d < 10; d++) w10[d] = __ldg(gc1_w + d * 512 + tid);
    float bb = __ldg(gc1_b + tid);
    for (int n = 0; n < 48; n++) {
        float a = bb;
        #pragma unroll
        for (int d = 0; d < 10; d++) a += w10[d] * sZ1[n * 10 + d];
        float v = ftanh(a);
        size_t idx = (size_t)(b * 48 + n) * 512 + tid;
        g_X[idx] = v;
        g_Af[idx] = __float2half_rn(v);
    }
}

// ===========================================================================
// Fused layer kernel: fp16x2 HMMA mainloop (m-tile 96 = 2 batches, n-tile 128)
// + in-SMEM epilogue: Y = [g_X +] tanh(att @ G + bias), emit fp16.
// ===========================================================================
#define ASTR 40                        // halfs per SMEM row (32 data + 8 pad)
#define STG_A  (96  * ASTR * 2)        // 7680 B (A fp16)
#define STG_B  (128 * ASTR * 2)        // 10240 B per W matrix
#define STG_SZ (STG_A + 2 * STG_B)     // 28160 B per stage
#define GEMM_SMEM 60416                // max(2*STG_SZ=56320, epilogue 59904)

__global__ void __launch_bounds__(256, 2)
layer_kernel(int layer, int residual, int emit,
             const float* __restrict__ att, const float* __restrict__ bias) {
    extern __shared__ __align__(16) char smem[];
    const int tid = threadIdx.x;
    const int lane = tid & 31, wid = tid >> 5;
    const int wm = wid >> 2, wn = wid & 3;
    const int n0 = blockIdx.x * 128;
    const int m0 = blockIdx.y * 96;           // 2 batches
    const uint32_t sbase = smem_u32(smem);

    const __half* Af = g_Af;
    const __half* Wh = g_Wh + layer * 262144;
    const __half* Wl = g_Wl + layer * 262144;

    float acc[3][4][4];
    #pragma unroll
    for (int i = 0; i < 3; i++)
        #pragma unroll
        for (int j = 0; j < 4; j++)
            #pragma unroll
            for (int r = 0; r < 4; r++) acc[i][j][r] = 0.f;

    // stage loader: (96 + 2*128) rows x 64B = 1408 16B-chunks (5.5 per thread)
    #define LOAD_STAGE(buf, ks) do { \
        uint32_t stg = sbase + (buf) * STG_SZ; \
        _Pragma("unroll") \
        for (int it = 0; it < 6; it++) { \
            int i = it * 256 + tid; \
            if (it == 5 && tid >= 128) break; \
            int r = i >> 2, q = i & 3; \
            uint32_t dst; const __half* src; \
            if (r < 96) { \
                dst = stg + r * 80 + q * 16; \
                src = Af + (size_t)(m0 + r) * 512 + (ks) * 32 + q * 8; \
            } else if (r < 224) { \
                dst = stg + STG_A + (r - 96) * 80 + q * 16; \
                src = Wh + (size_t)(n0 + r - 96) * 512 + (ks) * 32 + q * 8; \
            } else { \
                dst = stg + STG_A + STG_B + (r - 224) * 80 + q * 16; \
                src = Wl + (size_t)(n0 + r - 224) * 512 + (ks) * 32 + q * 8; \
            } \
            CPA16(dst, src); \
        } \
    } while (0)

    LOAD_STAGE(0, 0);
    CP_COMMIT();

    const int arow = wm * 48 + (lane & 15);
    const int acol = (lane >> 4) * 8;
    const int brow = wn * 32 + (lane & 7) + ((lane >> 4) & 1) * 8;
    const int bcol = ((lane >> 3) & 1) * 8;

    for (int ks = 0; ks < 16; ks++) {
        int buf = ks & 1;
        if (ks + 1 < 16) {
            LOAD_STAGE(buf ^ 1, ks + 1);
            CP_COMMIT();
            CP_WAIT(1);
        } else {
            CP_WAIT(0);
        }
        __syncthreads();

        uint32_t base = sbase + buf * STG_SZ;
        #pragma unroll
        for (int sub = 0; sub < 2; sub++) {
            int kb = sub * 16;
            uint32_t ah[3][4], bh[2][4], bl[2][4];
            #pragma unroll
            for (int mt = 0; mt < 3; mt++)
                LDSM4(ah[mt], base + (uint32_t)((arow + mt * 16) * ASTR + kb + acol) * 2);
            #pragma unroll
            for (int ng = 0; ng < 2; ng++) {
                LDSM4(bh[ng], base + STG_A + (uint32_t)((brow + ng * 16) * ASTR + kb + bcol) * 2);
                LDSM4(bl[ng], base + STG_A + STG_B + (uint32_t)((brow + ng * 16) * ASTR + kb + bcol) * 2);
            }
            #pragma unroll
            for (int mt = 0; mt < 3; mt++) {
                #pragma unroll
                for (int nf = 0; nf < 4; nf++) {
                    mma_f16(acc[mt][nf], ah[mt], &bh[nf >> 1][(nf & 1) * 2]);
                    mma_f16(acc[mt][nf], ah[mt], &bl[nf >> 1][(nf & 1) * 2]);
                }
            }
        }
        __syncthreads();
    }

    // ================= fused epilogue: att @ G + bias + tanh ===============
    float* sG = (float*)smem;                 // 96*132*4 = 50688 B
    float* sAttT = sG + 96 * 132;             // + 9216 = 59904 <= 60416

    #pragma unroll
    for (int mt = 0; mt < 3; mt++) {
        int row = wm * 48 + mt * 16 + (lane >> 2);
        #pragma unroll
        for (int nf = 0; nf < 4; nf++) {
            int col = wn * 32 + nf * 8 + (lane & 3) * 2;
            sG[row * 132 + col]           = acc[mt][nf][0];
            sG[row * 132 + col + 1]       = acc[mt][nf][1];
            sG[(row + 8) * 132 + col]     = acc[mt][nf][2];
            sG[(row + 8) * 132 + col + 1] = acc[mt][nf][3];
        }
    }
    for (int i = tid; i < 2304; i += 256) {
        int m = i / 48, n = i % 48;
        sAttT[m * 48 + n] = __ldg(att + n * 48 + m);
    }
    __syncthreads();

    {
        const int lc = tid & 127;             // local col 0..127
        const int b2 = tid >> 7;              // local batch 0/1
        float g[48];
        #pragma unroll
        for (int m = 0; m < 48; m++) g[m] = sG[(b2 * 48 + m) * 132 + lc];

        ull gacc[24];
        #pragma unroll
        for (int j = 0; j < 24; j++) gacc[j] = 0ull;
        #pragma unroll 4
        for (int m = 0; m < 48; m++) {
            ull gp = pk2(g[m], g[m]);
            const ull* ap = (const ull*)(sAttT + m * 48);
            #pragma unroll
            for (int j = 0; j < 24; j++) fma2f(gacc[j], ap[j], gp);
        }

        const int col = n0 + lc;
        const float bb = __ldg(bias + col);
        const size_t rowbase = (size_t)(m0 + b2 * 48) * 512 + col;
        #pragma unroll
        for (int j = 0; j < 24; j++) {
            float2 z = up2(gacc[j]);
            float v0 = ftanh(z.x + bb);
            float v1 = ftanh(z.y + bb);
            size_t i0 = rowbase + (size_t)(2 * j) * 512;
            size_t i1 = i0 + 512;
            if (residual) {
                v0 += g_X[i0];
                v1 += g_X[i1];
                g_X[i0] = v0;
                g_X[i1] = v1;
            }
            if (emit) {
                g_Af[i0] = __float2half_rn(v0);
                g_Af[i1] = __float2half_rn(v1);
            }
        }
    }
}

// ======================= tail: gc7 + fused + MLP ===========================
#define TAIL_SMEM ((480 + 480 + 480 + 5120 + 1920 + 12288) * 4)
__global__ void __launch_bounds__(512)
tail_kernel(const float* __restrict__ gc7_w, const float* __restrict__ gc7_att,
            const float* __restrict__ gc7_b, const float* __restrict__ mlp_w1,
            const float* __restrict__ mlp_w2, float* __restrict__ out) {
    extern __shared__ float sm[];
    float* sDct = sm;
    float* sP   = sDct + 480;
    float* sOut = sP + 480;
    float* sW7  = sOut + 480;      // [o][k] 10x512
    float* sFused = sW7 + 5120;    // 48x40
    float* sH   = sFused + 1920;   // 48x256
    const int tid = threadIdx.x, b = blockIdx.x;

    if (tid < 480) sDct[tid] = g_dct[b * 480 + tid];
    for (int i = tid; i < 5120; i += 512) {
        int o = i / 512, k = i % 512;
        sW7[o * 512 + k] = __ldg(gc7_w + k * 10 + o);
    }
    __syncthreads();
    if (tid < 480) {
        int m = tid / 10, o = tid % 10;
        const float* yr = g_X + (size_t)(b * 48 + m) * 512;
        const float* wr = sW7 + o * 512;
        float a0=0,a1=0,a2=0,a3=0;
        for (int k = 0; k < 512; k += 4) {
            float4 y4 = *(const float4*)(yr + k);
            float4 w4 = *(const float4*)(wr + k);
            a0 += y4.x*w4.x; a1 += y4.y*w4.y; a2 += y4.z*w4.z; a3 += y4.w*w4.w;
        }
        sP[tid] = a0 + a1 + a2 + a3;
    }
    __syncthreads();
    if (tid < 480) {
        int n = tid / 10, o = tid % 10;
        float a = __ldg(gc7_b + o) + sDct[tid];
        for (int m = 0; m < 48; m++) a += __ldg(gc7_att + n * 48 + m) * sP[m * 10 + o];
        sOut[tid] = a;
    }
    __syncthreads();
    for (int i = tid; i < 1920; i += 512) {
        int f = i % 48, t = i / 48;
        float v;
        if (t < 30) {
            v = 0.f;
            #pragma unroll
            for (int d = 0; d < 10; d++) {
                float wd = (d == 0) ? W0_DCT : W1_DCT;
                v += wd * cosf(PI_F * ((float)t + 0.5f) * (float)d / 30.0f)
                        * sOut[f * 10 + d];
            }
        } else v = g_ffc[b * 480 + f * 10 + (t - 30)];
        sFused[f * 40 + t] = v;
    }
    __syncthreads();
    {
        int o = tid & 255, fg = tid >> 8;
        float w1r[40];
        #pragma unroll
        for (int t = 0; t < 40; t++) w1r[t] = __ldg(mlp_w1 + o * 40 + t);
        for (int f = fg * 24; f < fg * 24 + 24; f++) {
            float a = 0.f;
            #pragma unroll
            for (int t = 0; t < 40; t++) a += w1r[t] * sFused[f * 40 + t];
            sH[f * 256 + o] = (a > 0.f) ? a : 0.f;
        }
    }
    __syncthreads();
    if (tid < 480) {
        int f = tid / 10, t2 = tid % 10;
        float a0=0,a1=0,a2=0,a3=0;
        const float* hr = sH + f * 256;
        const float* w2 = mlp_w2 + t2 * 256;
        for (int o = 0; o < 256; o += 4) {
            a0 += hr[o]*__ldg(w2+o);     a1 += hr[o+1]*__ldg(w2+o+1);
            a2 += hr[o+2]*__ldg(w2+o+2); a3 += hr[o+3]*__ldg(w2+o+3);
        }
        out[b * 480 + t2 * 48 + f] = a0 + a1 + a2 + a3;
    }
}

// ===========================================================================
extern "C" void kernel_launch(void* const* d_in, const int* in_sizes, int n_in,
                              void* d_out, int out_size) {
    const float* seq     = (const float*)d_in[0];
    const float* gc1_w   = (const float*)d_in[5];
    const float* gc1_att = (const float*)d_in[6];
    const float* gc1_b   = (const float*)d_in[7];
    const float* gcb_w   = (const float*)d_in[8];
    const float* gcb_att = (const float*)d_in[9];
    const float* gcb_b   = (const float*)d_in[10];
    const float* gc7_w   = (const float*)d_in[11];
    const float* gc7_att = (const float*)d_in[12];
    const float* gc7_b   = (const float*)d_in[13];
    const float* mlp_w1  = (const float*)d_in[14];
    const float* mlp_w2  = (const float*)d_in[15];
    const float* ffc_wl  = (const float*)d_in[16];
    const float* ffc_wg  = (const float*)d_in[17];
    float* out = (float*)d_out;

    int B = in_sizes[0] / 2400;           // 1024
    int gm = (B * 48) / 96;               // 512 m-tiles (2 batches each)

    cudaFuncSetAttribute(layer_kernel,
        cudaFuncAttributeMaxDynamicSharedMemorySize, GEMM_SMEM);
    cudaFuncSetAttribute(tail_kernel,
        cudaFuncAttributeMaxDynamicSharedMemorySize, TAIL_SMEM);

    prep_w_kernel<<<4096, 256>>>(gcb_w);
    ffc_kernel<<<B * 16, 64>>>(seq, ffc_wl, ffc_wg);
    gc1_kernel<<<B, 512>>>(seq, gc1_w, gc1_att, gc1_b);

    for (int l = 0; l < 4; l++) {
        layer_kernel<<<dim3(4, gm), 256, GEMM_SMEM>>>(
            l, l & 1, (l < 3) ? 1 : 0,
            gcb_att + l * 2304, gcb_b + l * 512);
    }
    tail_kernel<<<B, 512, TAIL_SMEM>>>(gc7_w, gc7_att, gc7_b,
                                       mlp_w1, mlp_w2, out);
}

// round 11
// speedup vs baseline: 1.6818x; 1.1918x over previous
#include <cuda_runtime.h>
#include <cuda_fp16.h>
#include <math.h>
#include <cstdint>

// ---------------------------------------------------------------------------
// DAFCN forward, B=1024, T=50, F=48, D=512.
// Attention branch (wq*/wk*, dvb, attended) dead: combined[:,:,:10] = gcn_out.
// R11: 3-stage cp.async pipeline in layer kernel; tail rewritten with
//      warp-shuffle dots (P phase + MLP2) and SMEM staging.
// ---------------------------------------------------------------------------

typedef unsigned long long ull;

#define PI_F 3.14159265358979f
#define W0_DCT 0.18257418583505537f
#define W1_DCT 0.2581988897471611f
#define NB 1024
#define MROWS (NB * 48)

__device__ float  g_X[MROWS * 512];       // fp32 y (residual carrier)
__device__ __half g_Af[MROWS * 512];      // fp16 gemm A operand (y or h)
__device__ __half g_Wh[4 * 512 * 512];    // W^T [l][n][k] fp16 hi
__device__ __half g_Wl[4 * 512 * 512];    // W^T [l][n][k] fp16 lo
__device__ float  g_dct[NB * 480];
__device__ float  g_ffc[NB * 480];

// ---- helpers --------------------------------------------------------------
__device__ __forceinline__ ull pk2(float lo, float hi) {
    ull r; asm("mov.b64 %0, {%1, %2};" : "=l"(r) : "f"(lo), "f"(hi)); return r;
}
__device__ __forceinline__ void fma2f(ull &d, ull a, ull b) {
    asm("fma.rn.f32x2 %0, %1, %2, %0;" : "+l"(d) : "l"(a), "l"(b));
}
__device__ __forceinline__ float2 up2(ull v) {
    float lo, hi; asm("mov.b64 {%0, %1}, %2;" : "=f"(lo), "=f"(hi) : "l"(v));
    return make_float2(lo, hi);
}
__device__ __forceinline__ uint32_t smem_u32(const void* p) {
    uint32_t a;
    asm("{ .reg .u64 t; cvta.to.shared.u64 t, %1; cvt.u32.u64 %0, t; }"
        : "=r"(a) : "l"(p));
    return a;
}
__device__ __forceinline__ float ftanh(float x) {
    return 1.0f - __fdividef(2.0f, __expf(2.0f * x) + 1.0f);
}

#define CPA16(dst, src) \
    asm volatile("cp.async.cg.shared.global [%0], [%1], 16;" \
                 :: "r"(dst), "l"(src))
#define CP_COMMIT() asm volatile("cp.async.commit_group;" ::: "memory")
#define CP_WAIT(n)  asm volatile("cp.async.wait_group %0;" :: "n"(n) : "memory")

#define LDSM4(r, addr) \
    asm volatile("ldmatrix.sync.aligned.m8n8.x4.shared.b16 {%0,%1,%2,%3}, [%4];" \
        : "=r"((r)[0]), "=r"((r)[1]), "=r"((r)[2]), "=r"((r)[3]) : "r"(addr))

__device__ __forceinline__ void mma_f16(float* d, const uint32_t* a,
                                        const uint32_t* b) {
    asm volatile(
        "mma.sync.aligned.m16n8k16.row.col.f32.f16.f16.f32 "
        "{%0,%1,%2,%3}, {%4,%5,%6,%7}, {%8,%9}, {%0,%1,%2,%3};"
        : "+f"(d[0]), "+f"(d[1]), "+f"(d[2]), "+f"(d[3])
        : "r"(a[0]), "r"(a[1]), "r"(a[2]), "r"(a[3]), "r"(b[0]), "r"(b[1]));
}

// ======================= prep_w: W^T fp16 hi/lo ============================
__global__ void prep_w_kernel(const float* __restrict__ gcb_w) {
    int idx = blockIdx.x * 256 + threadIdx.x;
    int l = idx >> 18, k = (idx >> 9) & 511, n = idx & 511;
    float w = gcb_w[l * 262144 + k * 512 + n];
    __half hi = __float2half_rn(w);
    __half lo = __float2half_rn(w - __half2float(hi));
    int dst = l * 262144 + n * 512 + k;
    g_Wh[dst] = hi; g_Wl[dst] = lo;
}

// ======================= FFC ===============================================
__global__ void ffc_kernel(const float* __restrict__ seq,
                           const float* __restrict__ wl,
                           const float* __restrict__ wg) {
    int bx = blockIdx.x, b = bx >> 4, g = bx & 15, tid = threadIdx.x;
    __shared__ float sXf[3][60], sV[6][31], sc[60], ss[60], sWg[36], sWl[9];
    if (tid < 60) {
        float a = 6.283185307179586f * (float)tid / 60.0f;
        sc[tid] = cosf(a); ss[tid] = sinf(a);
    }
    if (tid < 36) sWg[tid] = wg[tid];
    if (tid < 9)  sWl[tid] = wl[tid];
    for (int i = tid; i < 180; i += 64) {
        int c = i / 60, t = i % 60, tsrc = (t < 50) ? t : 49;
        sXf[c][t] = seq[b * 2400 + tsrc * 48 + c * 16 + g];
    }
    __syncthreads();
    if (tid < 31) {
        int k = tid;
        float re0=0,re1=0,re2=0,im0=0,im1=0,im2=0; int idx = 0;
        for (int t = 0; t < 60; t++) {
            float co = sc[idx], si = ss[idx];
            float x0 = sXf[0][t], x1 = sXf[1][t], x2 = sXf[2][t];
            re0 += x0*co; im0 -= x0*si; re1 += x1*co; im1 -= x1*si;
            re2 += x2*co; im2 -= x2*si;
            idx += k; if (idx >= 60) idx -= 60;
        }
        float U[6] = {re0, re1, re2, im0, im1, im2};
        #pragma unroll
        for (int o = 0; o < 6; o++) {
            float a = 0.f;
            #pragma unroll
            for (int c = 0; c < 6; c++) a += sWg[o * 6 + c] * U[c];
            sV[o][k] = (a > 0.f) ? a : 0.f;
        }
    }
    __syncthreads();
    if (tid < 30) {
        int o = tid / 10, t = tid % 10;
        float spec = sV[o][0] + ((t & 1) ? -sV[o][30] : sV[o][30]);
        int idx = t;
        for (int k = 1; k < 30; k++) {
            spec += 2.0f * (sV[o][k] * sc[idx] - sV[o + 3][k] * ss[idx]);
            idx += t; if (idx >= 60) idx -= 60;
        }
        float v = spec * (1.0f / 60.0f);
        #pragma unroll
        for (int c = 0; c < 3; c++) v += sWl[o * 3 + c] * sXf[c][t];
        g_ffc[b * 480 + (o * 16 + g) * 10 + t] = v;
    }
}

// ======================= gc1 head: y0 -> g_X + fp16 emit ===================
__global__ void __launch_bounds__(512)
gc1_kernel(const float* __restrict__ seq, const float* __restrict__ gc1_w,
           const float* __restrict__ gc1_att, const float* __restrict__ gc1_b) {
    __shared__ float sDct[480], sZ1[480];
    const int tid = threadIdx.x, b = blockIdx.x;
    const float* sq = seq + b * 2400;
    if (tid < 480) {
        int f = tid % 48, d = tid / 48;
        float wd = (d == 0) ? W0_DCT : W1_DCT;
        float acc = 0.f, Sd = 0.f;
        for (int k = 0; k < 30; k++) {
            float cv = wd * cosf(PI_F * ((float)k + 0.5f) * (float)d / 30.0f);
            if (k < 10) acc += cv * sq[(40 + k) * 48 + f];
            else        Sd  += cv;
        }
        acc += Sd * sq[49 * 48 + f];
        sDct[f * 10 + d] = acc;
        g_dct[b * 480 + f * 10 + d] = acc;
    }
    __syncthreads();
    if (tid < 480) {
        int n = tid / 10, d = tid % 10;
        float a = 0.f;
        for (int m = 0; m < 48; m++) a += __ldg(gc1_att + n * 48 + m) * sDct[m * 10 + d];
        sZ1[n * 10 + d] = a;
    }
    __syncthreads();
    float w10[10];
    #pragma unroll
    for (int d = 0; d < 10; d++) w10[d] = __ldg(gc1_w + d * 512 + tid);
    float bb = __ldg(gc1_b + tid);
    for (int n = 0; n < 48; n++) {
        float a = bb;
        #pragma unroll
        for (int d = 0; d < 10; d++) a += w10[d] * sZ1[n * 10 + d];
        float v = ftanh(a);
        size_t idx = (size_t)(b * 48 + n) * 512 + tid;
        g_X[idx] = v;
        g_Af[idx] = __float2half_rn(v);
    }
}

// ===========================================================================
// Fused layer kernel: fp16x2 HMMA, 3-stage cp.async pipeline, m-tile 96,
// n-tile 128, fused att+bias+tanh epilogue in SMEM.
// ===========================================================================
#define ASTR 40
#define STG_A  (96  * ASTR * 2)        // 7680 B
#define STG_B  (128 * ASTR * 2)        // 10240 B
#define STG_SZ (STG_A + 2 * STG_B)     // 28160 B
#define GEMM_SMEM (3 * STG_SZ)         // 84480 B (>= epilogue 59904)

__global__ void __launch_bounds__(256, 2)
layer_kernel(int layer, int residual, int emit,
             const float* __restrict__ att, const float* __restrict__ bias) {
    extern __shared__ __align__(16) char smem[];
    const int tid = threadIdx.x;
    const int lane = tid & 31, wid = tid >> 5;
    const int wm = wid >> 2, wn = wid & 3;
    const int n0 = blockIdx.x * 128;
    const int m0 = blockIdx.y * 96;
    const uint32_t sbase = smem_u32(smem);

    const __half* Af = g_Af;
    const __half* Wh = g_Wh + layer * 262144;
    const __half* Wl = g_Wl + layer * 262144;

    float acc[3][4][4];
    #pragma unroll
    for (int i = 0; i < 3; i++)
        #pragma unroll
        for (int j = 0; j < 4; j++)
            #pragma unroll
            for (int r = 0; r < 4; r++) acc[i][j][r] = 0.f;

    #define LOAD_STAGE(buf, ks) do { \
        uint32_t stg = sbase + (buf) * STG_SZ; \
        _Pragma("unroll") \
        for (int it = 0; it < 6; it++) { \
            int i = it * 256 + tid; \
            if (it == 5 && tid >= 128) break; \
            int r = i >> 2, q = i & 3; \
            uint32_t dst; const __half* src; \
            if (r < 96) { \
                dst = stg + r * 80 + q * 16; \
                src = Af + (size_t)(m0 + r) * 512 + (ks) * 32 + q * 8; \
            } else if (r < 224) { \
                dst = stg + STG_A + (r - 96) * 80 + q * 16; \
                src = Wh + (size_t)(n0 + r - 96) * 512 + (ks) * 32 + q * 8; \
            } else { \
                dst = stg + STG_A + STG_B + (r - 224) * 80 + q * 16; \
                src = Wl + (size_t)(n0 + r - 224) * 512 + (ks) * 32 + q * 8; \
            } \
            CPA16(dst, src); \
        } \
    } while (0)

    LOAD_STAGE(0, 0);
    CP_COMMIT();
    LOAD_STAGE(1, 1);
    CP_COMMIT();

    const int arow = wm * 48 + (lane & 15);
    const int acol = (lane >> 4) * 8;
    const int brow = wn * 32 + (lane & 7) + ((lane >> 4) & 1) * 8;
    const int bcol = ((lane >> 3) & 1) * 8;

    int buf = 0, ld = 2;
    #pragma unroll 1
    for (int ks = 0; ks < 16; ks++) {
        if (ks + 2 < 16) {
            CP_WAIT(1);
            __syncthreads();
            LOAD_STAGE(ld, ks + 2);
            CP_COMMIT();
        } else {
            CP_WAIT(0);
            __syncthreads();
        }

        uint32_t base = sbase + buf * STG_SZ;
        #pragma unroll
        for (int sub = 0; sub < 2; sub++) {
            int kb = sub * 16;
            uint32_t ah[3][4], bh[2][4], bl[2][4];
            #pragma unroll
            for (int mt = 0; mt < 3; mt++)
                LDSM4(ah[mt], base + (uint32_t)((arow + mt * 16) * ASTR + kb + acol) * 2);
            #pragma unroll
            for (int ng = 0; ng < 2; ng++) {
                LDSM4(bh[ng], base + STG_A + (uint32_t)((brow + ng * 16) * ASTR + kb + bcol) * 2);
                LDSM4(bl[ng], base + STG_A + STG_B + (uint32_t)((brow + ng * 16) * ASTR + kb + bcol) * 2);
            }
            #pragma unroll
            for (int mt = 0; mt < 3; mt++) {
                #pragma unroll
                for (int nf = 0; nf < 4; nf++) {
                    mma_f16(acc[mt][nf], ah[mt], &bh[nf >> 1][(nf & 1) * 2]);
                    mma_f16(acc[mt][nf], ah[mt], &bl[nf >> 1][(nf & 1) * 2]);
                }
            }
        }
        __syncthreads();
        buf = (buf == 2) ? 0 : buf + 1;
        ld  = (ld  == 2) ? 0 : ld  + 1;
    }

    // ================= fused epilogue: att @ G + bias + tanh ===============
    float* sG = (float*)smem;                 // 96*132*4 = 50688 B
    float* sAttT = sG + 96 * 132;             // + 9216 = 59904 <= 84480

    #pragma unroll
    for (int mt = 0; mt < 3; mt++) {
        int row = wm * 48 + mt * 16 + (lane >> 2);
        #pragma unroll
        for (int nf = 0; nf < 4; nf++) {
            int col = wn * 32 + nf * 8 + (lane & 3) * 2;
            sG[row * 132 + col]           = acc[mt][nf][0];
            sG[row * 132 + col + 1]       = acc[mt][nf][1];
            sG[(row + 8) * 132 + col]     = acc[mt][nf][2];
            sG[(row + 8) * 132 + col + 1] = acc[mt][nf][3];
        }
    }
    for (int i = tid; i < 2304; i += 256) {
        int m = i / 48, n = i % 48;
        sAttT[m * 48 + n] = __ldg(att + n * 48 + m);
    }
    __syncthreads();

    {
        const int lc = tid & 127;
        const int b2 = tid >> 7;
        float g[48];
        #pragma unroll
        for (int m = 0; m < 48; m++) g[m] = sG[(b2 * 48 + m) * 132 + lc];

        ull gacc[24];
        #pragma unroll
        for (int j = 0; j < 24; j++) gacc[j] = 0ull;
        #pragma unroll 4
        for (int m = 0; m < 48; m++) {
            ull gp = pk2(g[m], g[m]);
            const ull* ap = (const ull*)(sAttT + m * 48);
            #pragma unroll
            for (int j = 0; j < 24; j++) fma2f(gacc[j], ap[j], gp);
        }

        const int col = n0 + lc;
        const float bb = __ldg(bias + col);
        const size_t rowbase = (size_t)(m0 + b2 * 48) * 512 + col;
        #pragma unroll
        for (int j = 0; j < 24; j++) {
            float2 z = up2(gacc[j]);
            float v0 = ftanh(z.x + bb);
            float v1 = ftanh(z.y + bb);
            size_t i0 = rowbase + (size_t)(2 * j) * 512;
            size_t i1 = i0 + 512;
            if (residual) {
                v0 += g_X[i0];
                v1 += g_X[i1];
                g_X[i0] = v0;
                g_X[i1] = v1;
            }
            if (emit) {
                g_Af[i0] = __float2half_rn(v0);
                g_Af[i1] = __float2half_rn(v1);
            }
        }
    }
}

// ======================= tail: gc7 + fused + MLP (warp-dot version) ========
// SMEM floats: sY 24576 | sW7 5120 | sDct 480 | sP 480 | sOut 480 |
//              sFused 1920 | sW2 2560.  sH (12288) overlays sY after P phase.
#define TAIL_SMEM ((24576 + 5120 + 480 + 480 + 480 + 1920 + 2560) * 4)
__global__ void __launch_bounds__(512)
tail_kernel(const float* __restrict__ gc7_w, const float* __restrict__ gc7_att,
            const float* __restrict__ gc7_b, const float* __restrict__ mlp_w1,
            const float* __restrict__ mlp_w2, float* __restrict__ out) {
    extern __shared__ float sm[];
    float* sY    = sm;              // 24576 (reused as sH after P phase)
    float* sW7   = sm + 24576;      // 5120 [o][k]
    float* sDct  = sm + 29696;      // 480
    float* sP    = sm + 30176;      // 480
    float* sOut  = sm + 30656;      // 480
    float* sFused= sm + 31136;      // 1920
    float* sW2   = sm + 33056;      // 2560 [t2][o]
    float* sH    = sm;              // 12288 overlay

    const int tid = threadIdx.x, b = blockIdx.x;
    const int lane = tid & 31, w = tid >> 5;     // 16 warps

    // ---- stage loads ----
    {
        const float4* ysrc = (const float4*)(g_X + (size_t)b * 24576);
        float4* ydst = (float4*)sY;
        #pragma unroll
        for (int i = 0; i < 12; i++) ydst[tid + i * 512] = ysrc[tid + i * 512];
    }
    for (int i = tid; i < 5120; i += 512) {
        int o = i >> 9, k = i & 511;
        sW7[i] = __ldg(gc7_w + k * 10 + o);
    }
    for (int i = tid; i < 2560; i += 512) sW2[i] = __ldg(mlp_w2 + i);
    if (tid < 480) sDct[tid] = g_dct[b * 480 + tid];
    __syncthreads();

    // ---- P[m][o] = dot(y[m], w7[:,o])  (480 warp-dots) ----
    #pragma unroll 1
    for (int uu = 0; uu < 30; uu++) {
        int u = uu * 16 + w;
        int m = u / 10, o = u % 10;
        const float* yr = sY + m * 512;
        const float* wr = sW7 + o * 512;
        float a = 0.f;
        #pragma unroll
        for (int j = 0; j < 16; j++) a += yr[j * 32 + lane] * wr[j * 32 + lane];
        a += __shfl_xor_sync(0xFFFFFFFFu, a, 16);
        a += __shfl_xor_sync(0xFFFFFFFFu, a, 8);
        a += __shfl_xor_sync(0xFFFFFFFFu, a, 4);
        a += __shfl_xor_sync(0xFFFFFFFFu, a, 2);
        a += __shfl_xor_sync(0xFFFFFFFFu, a, 1);
        if (lane == 0) sP[u] = a;
    }
    __syncthreads();

    // ---- gcn_out[n][o] = b7[o] + dct[n][o] + sum_m att7[n][m] P[m][o] ----
    if (tid < 480) {
        int n = tid / 10, o = tid % 10;
        float a = __ldg(gc7_b + o) + sDct[tid];
        for (int m = 0; m < 48; m++) a += __ldg(gc7_att + n * 48 + m) * sP[m * 10 + o];
        sOut[tid] = a;
    }
    __syncthreads();

    // ---- fused[f][t]: t<30 idct(gcn_out), t>=30 ffc ----
    for (int i = tid; i < 1920; i += 512) {
        int f = i % 48, t = i / 48;
        float v;
        if (t < 30) {
            v = 0.f;
            #pragma unroll
            for (int d = 0; d < 10; d++) {
                float wd = (d == 0) ? W0_DCT : W1_DCT;
                v += wd * cosf(PI_F * ((float)t + 0.5f) * (float)d / 30.0f)
                        * sOut[f * 10 + d];
            }
        } else v = g_ffc[b * 480 + f * 10 + (t - 30)];
        sFused[f * 40 + t] = v;
    }
    __syncthreads();

    // ---- MLP1: h[f][o] = relu(dot(fused[f], w1[o])) -> sH (overlays sY) ----
    {
        int o = tid & 255, fg = tid >> 8;
        float w1r[40];
        #pragma unroll
        for (int t = 0; t < 40; t++) w1r[t] = __ldg(mlp_w1 + o * 40 + t);
        for (int f = fg * 24; f < fg * 24 + 24; f++) {
            float a = 0.f;
            #pragma unroll
            for (int t = 0; t < 40; t++) a += w1r[t] * sFused[f * 40 + t];
            sH[f * 256 + o] = (a > 0.f) ? a : 0.f;
        }
    }
    __syncthreads();

    // ---- MLP2 (t'<10): warp-dots of length 256 ----
    #pragma unroll 1
    for (int uu = 0; uu < 30; uu++) {
        int u = uu * 16 + w;
        int f = u / 10, t2 = u % 10;
        const float* hr = sH + f * 256;
        const float* wr = sW2 + t2 * 256;
        float a = 0.f;
        #pragma unroll
        for (int j = 0; j < 8; j++) a += hr[j * 32 + lane] * wr[j * 32 + lane];
        a += __shfl_xor_sync(0xFFFFFFFFu, a, 16);
        a += __shfl_xor_sync(0xFFFFFFFFu, a, 8);
        a += __shfl_xor_sync(0xFFFFFFFFu, a, 4);
        a += __shfl_xor_sync(0xFFFFFFFFu, a, 2);
        a += __shfl_xor_sync(0xFFFFFFFFu, a, 1);
        if (lane == 0) out[b * 480 + t2 * 48 + f] = a;
    }
}

// ===========================================================================
extern "C" void kernel_launch(void* const* d_in, const int* in_sizes, int n_in,
                              void* d_out, int out_size) {
    const float* seq     = (const float*)d_in[0];
    const float* gc1_w   = (const float*)d_in[5];
    const float* gc1_att = (const float*)d_in[6];
    const float* gc1_b   = (const float*)d_in[7];
    const float* gcb_w   = (const float*)d_in[8];
    const float* gcb_att = (const float*)d_in[9];
    const float* gcb_b   = (const float*)d_in[10];
    const float* gc7_w   = (const float*)d_in[11];
    const float* gc7_att = (const float*)d_in[12];
    const float* gc7_b   = (const float*)d_in[13];
    const float* mlp_w1  = (const float*)d_in[14];
    const float* mlp_w2  = (const float*)d_in[15];
    const float* ffc_wl  = (const float*)d_in[16];
    const float* ffc_wg  = (const float*)d_in[17];
    float* out = (float*)d_out;

    int B = in_sizes[0] / 2400;           // 1024
    int gm = (B * 48) / 96;               // 512 m-tiles

    cudaFuncSetAttribute(layer_kernel,
        cudaFuncAttributeMaxDynamicSharedMemorySize, GEMM_SMEM);
    cudaFuncSetAttribute(tail_kernel,
        cudaFuncAttributeMaxDynamicSharedMemorySize, TAIL_SMEM);

    prep_w_kernel<<<4096, 256>>>(gcb_w);
    ffc_kernel<<<B * 16, 64>>>(seq, ffc_wl, ffc_wg);
    gc1_kernel<<<B, 512>>>(seq, gc1_w, gc1_att, gc1_b);

    for (int l = 0; l < 4; l++) {
        layer_kernel<<<dim3(4, gm), 256, GEMM_SMEM>>>(
            l, l & 1, (l < 3) ? 1 : 0,
            gcb_att + l * 2304, gcb_b + l * 512);
    }
    tail_kernel<<<B, 512, TAIL_SMEM>>>(gc7_w, gc7_att, gc7_b,
                                       mlp_w1, mlp_w2, out);
}

// round 12
// speedup vs baseline: 1.9282x; 1.1465x over previous
#include <cuda_runtime.h>
#include <cuda_fp16.h>
#include <math.h>
#include <cstdint>

// ---------------------------------------------------------------------------
// DAFCN forward, B=1024, T=50, F=48, D=512.
// Attention branch (wq*/wk*, dvb, attended) dead: combined[:,:,:10] = gcn_out.
// R12: single-pass fp16 GEMM (W lo-split dropped; measured error attenuation
//      from R10 shows GEMM-level 1e-4 perturbations reach the output at ~2e-6).
//      4-stage cp.async pipeline, fused att+bias+tanh epilogue, warp-dot tail.
// ---------------------------------------------------------------------------

typedef unsigned long long ull;

#define PI_F 3.14159265358979f
#define W0_DCT 0.18257418583505537f
#define W1_DCT 0.2581988897471611f
#define NB 1024
#define MROWS (NB * 48)

__device__ float  g_X[MROWS * 512];       // fp32 y (residual carrier)
__device__ __half g_Af[MROWS * 512];      // fp16 gemm A operand (y or h)
__device__ __half g_Wh[4 * 512 * 512];    // W^T [l][n][k] fp16
__device__ float  g_dct[NB * 480];
__device__ float  g_ffc[NB * 480];

// ---- helpers --------------------------------------------------------------
__device__ __forceinline__ ull pk2(float lo, float hi) {
    ull r; asm("mov.b64 %0, {%1, %2};" : "=l"(r) : "f"(lo), "f"(hi)); return r;
}
__device__ __forceinline__ void fma2f(ull &d, ull a, ull b) {
    asm("fma.rn.f32x2 %0, %1, %2, %0;" : "+l"(d) : "l"(a), "l"(b));
}
__device__ __forceinline__ float2 up2(ull v) {
    float lo, hi; asm("mov.b64 {%0, %1}, %2;" : "=f"(lo), "=f"(hi) : "l"(v));
    return make_float2(lo, hi);
}
__device__ __forceinline__ uint32_t smem_u32(const void* p) {
    uint32_t a;
    asm("{ .reg .u64 t; cvta.to.shared.u64 t, %1; cvt.u32.u64 %0, t; }"
        : "=r"(a) : "l"(p));
    return a;
}
__device__ __forceinline__ float ftanh(float x) {
    return 1.0f - __fdividef(2.0f, __expf(2.0f * x) + 1.0f);
}

#define CPA16(dst, src) \
    asm volatile("cp.async.cg.shared.global [%0], [%1], 16;" \
                 :: "r"(dst), "l"(src))
#define CP_COMMIT() asm volatile("cp.async.commit_group;" ::: "memory")
#define CP_WAIT(n)  asm volatile("cp.async.wait_group %0;" :: "n"(n) : "memory")

#define LDSM4(r, addr) \
    asm volatile("ldmatrix.sync.aligned.m8n8.x4.shared.b16 {%0,%1,%2,%3}, [%4];" \
        : "=r"((r)[0]), "=r"((r)[1]), "=r"((r)[2]), "=r"((r)[3]) : "r"(addr))

__device__ __forceinline__ void mma_f16(float* d, const uint32_t* a,
                                        const uint32_t* b) {
    asm volatile(
        "mma.sync.aligned.m16n8k16.row.col.f32.f16.f16.f32 "
        "{%0,%1,%2,%3}, {%4,%5,%6,%7}, {%8,%9}, {%0,%1,%2,%3};"
        : "+f"(d[0]), "+f"(d[1]), "+f"(d[2]), "+f"(d[3])
        : "r"(a[0]), "r"(a[1]), "r"(a[2]), "r"(a[3]), "r"(b[0]), "r"(b[1]));
}

// ======================= prep_w: W^T fp16 ==================================
__global__ void prep_w_kernel(const float* __restrict__ gcb_w) {
    int idx = blockIdx.x * 256 + threadIdx.x;
    int l = idx >> 18, k = (idx >> 9) & 511, n = idx & 511;
    float w = gcb_w[l * 262144 + k * 512 + n];
    g_Wh[l * 262144 + n * 512 + k] = __float2half_rn(w);
}

// ======================= FFC ===============================================
__global__ void ffc_kernel(const float* __restrict__ seq,
                           const float* __restrict__ wl,
                           const float* __restrict__ wg) {
    int bx = blockIdx.x, b = bx >> 4, g = bx & 15, tid = threadIdx.x;
    __shared__ float sXf[3][60], sV[6][31], sc[60], ss[60], sWg[36], sWl[9];
    if (tid < 60) {
        float a = 6.283185307179586f * (float)tid / 60.0f;
        sc[tid] = cosf(a); ss[tid] = sinf(a);
    }
    if (tid < 36) sWg[tid] = wg[tid];
    if (tid < 9)  sWl[tid] = wl[tid];
    for (int i = tid; i < 180; i += 64) {
        int c = i / 60, t = i % 60, tsrc = (t < 50) ? t : 49;
        sXf[c][t] = seq[b * 2400 + tsrc * 48 + c * 16 + g];
    }
    __syncthreads();
    if (tid < 31) {
        int k = tid;
        float re0=0,re1=0,re2=0,im0=0,im1=0,im2=0; int idx = 0;
        for (int t = 0; t < 60; t++) {
            float co = sc[idx], si = ss[idx];
            float x0 = sXf[0][t], x1 = sXf[1][t], x2 = sXf[2][t];
            re0 += x0*co; im0 -= x0*si; re1 += x1*co; im1 -= x1*si;
            re2 += x2*co; im2 -= x2*si;
            idx += k; if (idx >= 60) idx -= 60;
        }
        float U[6] = {re0, re1, re2, im0, im1, im2};
        #pragma unroll
        for (int o = 0; o < 6; o++) {
            float a = 0.f;
            #pragma unroll
            for (int c = 0; c < 6; c++) a += sWg[o * 6 + c] * U[c];
            sV[o][k] = (a > 0.f) ? a : 0.f;
        }
    }
    __syncthreads();
    if (tid < 30) {
        int o = tid / 10, t = tid % 10;
        float spec = sV[o][0] + ((t & 1) ? -sV[o][30] : sV[o][30]);
        int idx = t;
        for (int k = 1; k < 30; k++) {
            spec += 2.0f * (sV[o][k] * sc[idx] - sV[o + 3][k] * ss[idx]);
            idx += t; if (idx >= 60) idx -= 60;
        }
        float v = spec * (1.0f / 60.0f);
        #pragma unroll
        for (int c = 0; c < 3; c++) v += sWl[o * 3 + c] * sXf[c][t];
        g_ffc[b * 480 + (o * 16 + g) * 10 + t] = v;
    }
}

// ======================= gc1 head: y0 -> g_X + fp16 emit ===================
__global__ void __launch_bounds__(512)
gc1_kernel(const float* __restrict__ seq, const float* __restrict__ gc1_w,
           const float* __restrict__ gc1_att, const float* __restrict__ gc1_b) {
    __shared__ float sDct[480], sZ1[480];
    const int tid = threadIdx.x, b = blockIdx.x;
    const float* sq = seq + b * 2400;
    if (tid < 480) {
        int f = tid % 48, d = tid / 48;
        float wd = (d == 0) ? W0_DCT : W1_DCT;
        float acc = 0.f, Sd = 0.f;
        for (int k = 0; k < 30; k++) {
            float cv = wd * cosf(PI_F * ((float)k + 0.5f) * (float)d / 30.0f);
            if (k < 10) acc += cv * sq[(40 + k) * 48 + f];
            else        Sd  += cv;
        }
        acc += Sd * sq[49 * 48 + f];
        sDct[f * 10 + d] = acc;
        g_dct[b * 480 + f * 10 + d] = acc;
    }
    __syncthreads();
    if (tid < 480) {
        int n = tid / 10, d = tid % 10;
        float a = 0.f;
        for (int m = 0; m < 48; m++) a += __ldg(gc1_att + n * 48 + m) * sDct[m * 10 + d];
        sZ1[n * 10 + d] = a;
    }
    __syncthreads();
    float w10[10];
    #pragma unroll
    for (int d = 0; d < 10; d++) w10[d] = __ldg(gc1_w + d * 512 + tid);
    float bb = __ldg(gc1_b + tid);
    for (int n = 0; n < 48; n++) {
        float a = bb;
        #pragma unroll
        for (int d = 0; d < 10; d++) a += w10[d] * sZ1[n * 10 + d];
        float v = ftanh(a);
        size_t idx = (size_t)(b * 48 + n) * 512 + tid;
        g_X[idx] = v;
        g_Af[idx] = __float2half_rn(v);
    }
}

// ===========================================================================
// Fused layer kernel: single-pass fp16 HMMA, 4-stage cp.async pipeline,
// m-tile 96 (2 batches), n-tile 128, fused att+bias+tanh epilogue in SMEM.
// ===========================================================================
#define ASTR 40
#define STG_A  (96  * ASTR * 2)        // 7680 B
#define STG_B  (128 * ASTR * 2)        // 10240 B
#define STG_SZ (STG_A + STG_B)         // 17920 B
#define GEMM_SMEM (4 * STG_SZ)         // 71680 B (>= epilogue 59904)

__global__ void __launch_bounds__(256, 2)
layer_kernel(int layer, int residual, int emit,
             const float* __restrict__ att, const float* __restrict__ bias) {
    extern __shared__ __align__(16) char smem[];
    const int tid = threadIdx.x;
    const int lane = tid & 31, wid = tid >> 5;
    const int wm = wid >> 2, wn = wid & 3;
    const int n0 = blockIdx.x * 128;
    const int m0 = blockIdx.y * 96;
    const uint32_t sbase = smem_u32(smem);

    const __half* Af = g_Af;
    const __half* Wh = g_Wh + layer * 262144;

    float acc[3][4][4];
    #pragma unroll
    for (int i = 0; i < 3; i++)
        #pragma unroll
        for (int j = 0; j < 4; j++)
            #pragma unroll
            for (int r = 0; r < 4; r++) acc[i][j][r] = 0.f;

    // stage loader: (96 A + 128 B) rows x 64B = 896 16B-chunks (3.5/thread)
    #define LOAD_STAGE(buf, ks) do { \
        uint32_t stg = sbase + (buf) * STG_SZ; \
        _Pragma("unroll") \
        for (int it = 0; it < 4; it++) { \
            int i = it * 256 + tid; \
            if (it == 3 && tid >= 128) break; \
            int r = i >> 2, q = i & 3; \
            uint32_t dst; const __half* src; \
            if (r < 96) { \
                dst = stg + r * 80 + q * 16; \
                src = Af + (size_t)(m0 + r) * 512 + (ks) * 32 + q * 8; \
            } else { \
                dst = stg + STG_A + (r - 96) * 80 + q * 16; \
                src = Wh + (size_t)(n0 + r - 96) * 512 + (ks) * 32 + q * 8; \
            } \
            CPA16(dst, src); \
        } \
    } while (0)

    LOAD_STAGE(0, 0); CP_COMMIT();
    LOAD_STAGE(1, 1); CP_COMMIT();
    LOAD_STAGE(2, 2); CP_COMMIT();

    const int arow = wm * 48 + (lane & 15);
    const int acol = (lane >> 4) * 8;
    const int brow = wn * 32 + (lane & 7) + ((lane >> 4) & 1) * 8;
    const int bcol = ((lane >> 3) & 1) * 8;

    int buf = 0, ld = 3;
    #pragma unroll 1
    for (int ks = 0; ks < 16; ks++) {
        if (ks + 3 < 16) {
            CP_WAIT(2);
            __syncthreads();
            LOAD_STAGE(ld, ks + 3);
            CP_COMMIT();
        } else {
            CP_WAIT(0);
            __syncthreads();
        }

        uint32_t base = sbase + buf * STG_SZ;
        #pragma unroll
        for (int sub = 0; sub < 2; sub++) {
            int kb = sub * 16;
            uint32_t ah[3][4], bh[2][4];
            #pragma unroll
            for (int mt = 0; mt < 3; mt++)
                LDSM4(ah[mt], base + (uint32_t)((arow + mt * 16) * ASTR + kb + acol) * 2);
            #pragma unroll
            for (int ng = 0; ng < 2; ng++)
                LDSM4(bh[ng], base + STG_A + (uint32_t)((brow + ng * 16) * ASTR + kb + bcol) * 2);
            #pragma unroll
            for (int mt = 0; mt < 3; mt++) {
                #pragma unroll
                for (int nf = 0; nf < 4; nf++)
                    mma_f16(acc[mt][nf], ah[mt], &bh[nf >> 1][(nf & 1) * 2]);
            }
        }
        __syncthreads();
        buf = (buf + 1) & 3;
        ld  = (ld  + 1) & 3;
    }

    // ================= fused epilogue: att @ G + bias + tanh ===============
    float* sG = (float*)smem;                 // 96*132*4 = 50688 B
    float* sAttT = sG + 96 * 132;             // + 9216 = 59904 <= 71680

    #pragma unroll
    for (int mt = 0; mt < 3; mt++) {
        int row = wm * 48 + mt * 16 + (lane >> 2);
        #pragma unroll
        for (int nf = 0; nf < 4; nf++) {
            int col = wn * 32 + nf * 8 + (lane & 3) * 2;
            sG[row * 132 + col]           = acc[mt][nf][0];
            sG[row * 132 + col + 1]       = acc[mt][nf][1];
            sG[(row + 8) * 132 + col]     = acc[mt][nf][2];
            sG[(row + 8) * 132 + col + 1] = acc[mt][nf][3];
        }
    }
    for (int i = tid; i < 2304; i += 256) {
        int m = i / 48, n = i % 48;
        sAttT[m * 48 + n] = __ldg(att + n * 48 + m);
    }
    __syncthreads();

    {
        const int lc = tid & 127;
        const int b2 = tid >> 7;
        float g[48];
        #pragma unroll
        for (int m = 0; m < 48; m++) g[m] = sG[(b2 * 48 + m) * 132 + lc];

        ull gacc[24];
        #pragma unroll
        for (int j = 0; j < 24; j++) gacc[j] = 0ull;
        #pragma unroll 4
        for (int m = 0; m < 48; m++) {
            ull gp = pk2(g[m], g[m]);
            const ull* ap = (const ull*)(sAttT + m * 48);
            #pragma unroll
            for (int j = 0; j < 24; j++) fma2f(gacc[j], ap[j], gp);
        }

        const int col = n0 + lc;
        const float bb = __ldg(bias + col);
        const size_t rowbase = (size_t)(m0 + b2 * 48) * 512 + col;
        #pragma unroll
        for (int j = 0; j < 24; j++) {
            float2 z = up2(gacc[j]);
            float v0 = ftanh(z.x + bb);
            float v1 = ftanh(z.y + bb);
            size_t i0 = rowbase + (size_t)(2 * j) * 512;
            size_t i1 = i0 + 512;
            if (residual) {
                v0 += g_X[i0];
                v1 += g_X[i1];
                g_X[i0] = v0;
                g_X[i1] = v1;
            }
            if (emit) {
                g_Af[i0] = __float2half_rn(v0);
                g_Af[i1] = __float2half_rn(v1);
            }
        }
    }
}

// ======================= tail: gc7 + fused + MLP (warp-dot) ================
#define TAIL_SMEM ((24576 + 5120 + 480 + 480 + 480 + 1920 + 2560) * 4)
__global__ void __launch_bounds__(512)
tail_kernel(const float* __restrict__ gc7_w, const float* __restrict__ gc7_att,
            const float* __restrict__ gc7_b, const float* __restrict__ mlp_w1,
            const float* __restrict__ mlp_w2, float* __restrict__ out) {
    extern __shared__ float sm[];
    float* sY    = sm;              // 24576 (reused as sH after P phase)
    float* sW7   = sm + 24576;      // 5120 [o][k]
    float* sDct  = sm + 29696;      // 480
    float* sP    = sm + 30176;      // 480
    float* sOut  = sm + 30656;      // 480
    float* sFused= sm + 31136;      // 1920
    float* sW2   = sm + 33056;      // 2560 [t2][o]
    float* sH    = sm;              // 12288 overlay

    const int tid = threadIdx.x, b = blockIdx.x;
    const int lane = tid & 31, w = tid >> 5;     // 16 warps

    {
        const float4* ysrc = (const float4*)(g_X + (size_t)b * 24576);
        float4* ydst = (float4*)sY;
        #pragma unroll
        for (int i = 0; i < 12; i++) ydst[tid + i * 512] = ysrc[tid + i * 512];
    }
    for (int i = tid; i < 5120; i += 512) {
        int o = i >> 9, k = i & 511;
        sW7[i] = __ldg(gc7_w + k * 10 + o);
    }
    for (int i = tid; i < 2560; i += 512) sW2[i] = __ldg(mlp_w2 + i);
    if (tid < 480) sDct[tid] = g_dct[b * 480 + tid];
    __syncthreads();

    #pragma unroll 1
    for (int uu = 0; uu < 30; uu++) {
        int u = uu * 16 + w;
        int m = u / 10, o = u % 10;
        const float* yr = sY + m * 512;
        const float* wr = sW7 + o * 512;
        float a = 0.f;
        #pragma unroll
        for (int j = 0; j < 16; j++) a += yr[j * 32 + lane] * wr[j * 32 + lane];
        a += __shfl_xor_sync(0xFFFFFFFFu, a, 16);
        a += __shfl_xor_sync(0xFFFFFFFFu, a, 8);
        a += __shfl_xor_sync(0xFFFFFFFFu, a, 4);
        a += __shfl_xor_sync(0xFFFFFFFFu, a, 2);
        a += __shfl_xor_sync(0xFFFFFFFFu, a, 1);
        if (lane == 0) sP[u] = a;
    }
    __syncthreads();

    if (tid < 480) {
        int n = tid / 10, o = tid % 10;
        float a = __ldg(gc7_b + o) + sDct[tid];
        for (int m = 0; m < 48; m++) a += __ldg(gc7_att + n * 48 + m) * sP[m * 10 + o];
        sOut[tid] = a;
    }
    __syncthreads();

    for (int i = tid; i < 1920; i += 512) {
        int f = i % 48, t = i / 48;
        float v;
        if (t < 30) {
            v = 0.f;
            #pragma unroll
            for (int d = 0; d < 10; d++) {
                float wd = (d == 0) ? W0_DCT : W1_DCT;
                v += wd * cosf(PI_F * ((float)t + 0.5f) * (float)d / 30.0f)
                        * sOut[f * 10 + d];
            }
        } else v = g_ffc[b * 480 + f * 10 + (t - 30)];
        sFused[f * 40 + t] = v;
    }
    __syncthreads();

    {
        int o = tid & 255, fg = tid >> 8;
        float w1r[40];
        #pragma unroll
        for (int t = 0; t < 40; t++) w1r[t] = __ldg(mlp_w1 + o * 40 + t);
        for (int f = fg * 24; f < fg * 24 + 24; f++) {
            float a = 0.f;
            #pragma unroll
            for (int t = 0; t < 40; t++) a += w1r[t] * sFused[f * 40 + t];
            sH[f * 256 + o] = (a > 0.f) ? a : 0.f;
        }
    }
    __syncthreads();

    #pragma unroll 1
    for (int uu = 0; uu < 30; uu++) {
        int u = uu * 16 + w;
        int f = u / 10, t2 = u % 10;
        const float* hr = sH + f * 256;
        const float* wr = sW2 + t2 * 256;
        float a = 0.f;
        #pragma unroll
        for (int j = 0; j < 8; j++) a += hr[j * 32 + lane] * wr[j * 32 + lane];
        a += __shfl_xor_sync(0xFFFFFFFFu, a, 16);
        a += __shfl_xor_sync(0xFFFFFFFFu, a, 8);
        a += __shfl_xor_sync(0xFFFFFFFFu, a, 4);
        a += __shfl_xor_sync(0xFFFFFFFFu, a, 2);
        a += __shfl_xor_sync(0xFFFFFFFFu, a, 1);
        if (lane == 0) out[b * 480 + t2 * 48 + f] = a;
    }
}

// ===========================================================================
extern "C" void kernel_launch(void* const* d_in, const int* in_sizes, int n_in,
                              void* d_out, int out_size) {
    const float* seq     = (const float*)d_in[0];
    const float* gc1_w   = (const float*)d_in[5];
    const float* gc1_att = (const float*)d_in[6];
    const float* gc1_b   = (const float*)d_in[7];
    const float* gcb_w   = (const float*)d_in[8];
    const float* gcb_att = (const float*)d_in[9];
    const float* gcb_b   = (const float*)d_in[10];
    const float* gc7_w   = (const float*)d_in[11];
    const float* gc7_att = (const float*)d_in[12];
    const float* gc7_b   = (const float*)d_in[13];
    const float* mlp_w1  = (const float*)d_in[14];
    const float* mlp_w2  = (const float*)d_in[15];
    const float* ffc_wl  = (const float*)d_in[16];
    const float* ffc_wg  = (const float*)d_in[17];
    float* out = (float*)d_out;

    int B = in_sizes[0] / 2400;           // 1024
    int gm = (B * 48) / 96;               // 512 m-tiles

    cudaFuncSetAttribute(layer_kernel,
        cudaFuncAttributeMaxDynamicSharedMemorySize, GEMM_SMEM);
    cudaFuncSetAttribute(tail_kernel,
        cudaFuncAttributeMaxDynamicSharedMemorySize, TAIL_SMEM);

    prep_w_kernel<<<4096, 256>>>(gcb_w);
    ffc_kernel<<<B * 16, 64>>>(seq, ffc_wl, ffc_wg);
    gc1_kernel<<<B, 512>>>(seq, gc1_w, gc1_att, gc1_b);

    for (int l = 0; l < 4; l++) {
        layer_kernel<<<dim3(4, gm), 256, GEMM_SMEM>>>(
            l, l & 1, (l < 3) ? 1 : 0,
            gcb_att + l * 2304, gcb_b + l * 512);
    }
    tail_kernel<<<B, 512, TAIL_SMEM>>>(gc7_w, gc7_att, gc7_b,
                                       mlp_w1, mlp_w2, out);
}

// round 13
// speedup vs baseline: 1.9346x; 1.0034x over previous
#include <cuda_runtime.h>
#include <cuda_fp16.h>
#include <math.h>
#include <cstdint>

// ---------------------------------------------------------------------------
// DAFCN forward, B=1024, T=50, F=48, D=512.
// Attention branch (wq*/wk*, dvb, attended) dead: combined[:,:,:10] = gcn_out.
// R13: single-sync 4-stage mainloop; ffc+gc1 merged into head_kernel
//      (1 block/batch, dense thread utilization). Single-pass fp16 HMMA,
//      fused att+bias+tanh epilogue, warp-dot tail.
// ---------------------------------------------------------------------------

typedef unsigned long long ull;

#define PI_F 3.14159265358979f
#define W0_DCT 0.18257418583505537f
#define W1_DCT 0.2581988897471611f
#define NB 1024
#define MROWS (NB * 48)

__device__ float  g_X[MROWS * 512];       // fp32 y (residual carrier)
__device__ __half g_Af[MROWS * 512];      // fp16 gemm A operand (y or h)
__device__ __half g_Wh[4 * 512 * 512];    // W^T [l][n][k] fp16
__device__ float  g_dct[NB * 480];
__device__ float  g_ffc[NB * 480];

// ---- helpers --------------------------------------------------------------
__device__ __forceinline__ ull pk2(float lo, float hi) {
    ull r; asm("mov.b64 %0, {%1, %2};" : "=l"(r) : "f"(lo), "f"(hi)); return r;
}
__device__ __forceinline__ void fma2f(ull &d, ull a, ull b) {
    asm("fma.rn.f32x2 %0, %1, %2, %0;" : "+l"(d) : "l"(a), "l"(b));
}
__device__ __forceinline__ float2 up2(ull v) {
    float lo, hi; asm("mov.b64 {%0, %1}, %2;" : "=f"(lo), "=f"(hi) : "l"(v));
    return make_float2(lo, hi);
}
__device__ __forceinline__ uint32_t smem_u32(const void* p) {
    uint32_t a;
    asm("{ .reg .u64 t; cvta.to.shared.u64 t, %1; cvt.u32.u64 %0, t; }"
        : "=r"(a) : "l"(p));
    return a;
}
__device__ __forceinline__ float ftanh(float x) {
    return 1.0f - __fdividef(2.0f, __expf(2.0f * x) + 1.0f);
}

#define CPA16(dst, src) \
    asm volatile("cp.async.cg.shared.global [%0], [%1], 16;" \
                 :: "r"(dst), "l"(src))
#define CP_COMMIT() asm volatile("cp.async.commit_group;" ::: "memory")
#define CP_WAIT(n)  asm volatile("cp.async.wait_group %0;" :: "n"(n) : "memory")

#define LDSM4(r, addr) \
    asm volatile("ldmatrix.sync.aligned.m8n8.x4.shared.b16 {%0,%1,%2,%3}, [%4];" \
        : "=r"((r)[0]), "=r"((r)[1]), "=r"((r)[2]), "=r"((r)[3]) : "r"(addr))

__device__ __forceinline__ void mma_f16(float* d, const uint32_t* a,
                                        const uint32_t* b) {
    asm volatile(
        "mma.sync.aligned.m16n8k16.row.col.f32.f16.f16.f32 "
        "{%0,%1,%2,%3}, {%4,%5,%6,%7}, {%8,%9}, {%0,%1,%2,%3};"
        : "+f"(d[0]), "+f"(d[1]), "+f"(d[2]), "+f"(d[3])
        : "r"(a[0]), "r"(a[1]), "r"(a[2]), "r"(a[3]), "r"(b[0]), "r"(b[1]));
}

// ======================= prep_w: W^T fp16 ==================================
__global__ void prep_w_kernel(const float* __restrict__ gcb_w) {
    int idx = blockIdx.x * 256 + threadIdx.x;
    int l = idx >> 18, k = (idx >> 9) & 511, n = idx & 511;
    float w = gcb_w[l * 262144 + k * 512 + n];
    g_Wh[l * 262144 + n * 512 + k] = __float2half_rn(w);
}

// ======================= head: FFC + gc1 (1 block / batch) =================
__global__ void __launch_bounds__(512)
head_kernel(const float* __restrict__ seq,
            const float* __restrict__ wl,  const float* __restrict__ wg,
            const float* __restrict__ gc1_w, const float* __restrict__ gc1_att,
            const float* __restrict__ gc1_b) {
    __shared__ float sSeq[2400];           // [t][f] t<50
    __shared__ float sc[60], ss[60];
    __shared__ float sV[16][6][31];        // g, (re0..2,im0..2), k
    __shared__ float sWg[36], sWl[9];
    __shared__ float sDct[480], sZ1[480];

    const int tid = threadIdx.x, b = blockIdx.x;

    for (int i = tid; i < 2400; i += 512) sSeq[i] = seq[b * 2400 + i];
    if (tid < 60) {
        float a = 6.283185307179586f * (float)tid / 60.0f;
        sc[tid] = cosf(a); ss[tid] = sinf(a);
    }
    if (tid < 36) sWg[tid] = wg[tid];
    if (tid < 9)  sWl[tid] = wl[tid];
    __syncthreads();

    // ---- DFT phase: g = tid>>5, k = tid&31 (k<31 active) ----
    if ((tid & 31) < 31) {
        const int g = tid >> 5, k = tid & 31;
        float re0=0,re1=0,re2=0,im0=0,im1=0,im2=0;
        int idx = 0;
        for (int t = 0; t < 60; t++) {
            int tsrc = (t < 50) ? t : 49;
            float co = sc[idx], si = ss[idx];
            float x0 = sSeq[tsrc * 48 + g];
            float x1 = sSeq[tsrc * 48 + 16 + g];
            float x2 = sSeq[tsrc * 48 + 32 + g];
            re0 += x0*co; im0 -= x0*si;
            re1 += x1*co; im1 -= x1*si;
            re2 += x2*co; im2 -= x2*si;
            idx += k; if (idx >= 60) idx -= 60;
        }
        float U[6] = {re0, re1, re2, im0, im1, im2};
        #pragma unroll
        for (int o = 0; o < 6; o++) {
            float a = 0.f;
            #pragma unroll
            for (int c = 0; c < 6; c++) a += sWg[o * 6 + c] * U[c];
            sV[g][o][k] = (a > 0.f) ? a : 0.f;
        }
    }
    __syncthreads();

    // ---- irfft + local mix: tid<480 -> (g, o, t) ----
    if (tid < 480) {
        const int g = tid / 30, r = tid % 30, o = r / 10, t = r % 10;
        float spec = sV[g][o][0] + ((t & 1) ? -sV[g][o][30] : sV[g][o][30]);
        int idx = t;
        for (int k = 1; k < 30; k++) {
            spec += 2.0f * (sV[g][o][k] * sc[idx] - sV[g][o + 3][k] * ss[idx]);
            idx += t; if (idx >= 60) idx -= 60;
        }
        float v = spec * (1.0f / 60.0f);
        #pragma unroll
        for (int c = 0; c < 3; c++) v += sWl[o * 3 + c] * sSeq[t * 48 + c * 16 + g];
        g_ffc[b * 480 + (o * 16 + g) * 10 + t] = v;
    }

    // ---- gc1: dct_in ----
    if (tid < 480) {
        int f = tid % 48, d = tid / 48;
        float wd = (d == 0) ? W0_DCT : W1_DCT;
        float acc = 0.f, Sd = 0.f;
        for (int k = 0; k < 30; k++) {
            float cv = wd * cosf(PI_F * ((float)k + 0.5f) * (float)d / 30.0f);
            if (k < 10) acc += cv * sSeq[(40 + k) * 48 + f];
            else        Sd  += cv;
        }
        acc += Sd * sSeq[49 * 48 + f];
        sDct[f * 10 + d] = acc;
        g_dct[b * 480 + f * 10 + d] = acc;
    }
    __syncthreads();
    if (tid < 480) {
        int n = tid / 10, d = tid % 10;
        float a = 0.f;
        for (int m = 0; m < 48; m++) a += __ldg(gc1_att + n * 48 + m) * sDct[m * 10 + d];
        sZ1[n * 10 + d] = a;
    }
    __syncthreads();
    {
        float w10[10];
        #pragma unroll
        for (int d = 0; d < 10; d++) w10[d] = __ldg(gc1_w + d * 512 + tid);
        float bb = __ldg(gc1_b + tid);
        for (int n = 0; n < 48; n++) {
            float a = bb;
            #pragma unroll
            for (int d = 0; d < 10; d++) a += w10[d] * sZ1[n * 10 + d];
            float v = ftanh(a);
            size_t idx = (size_t)(b * 48 + n) * 512 + tid;
            g_X[idx] = v;
            g_Af[idx] = __float2half_rn(v);
        }
    }
}

// ===========================================================================
// Fused layer kernel: single-pass fp16 HMMA, 4-stage single-sync pipeline,
// m-tile 96 (2 batches), n-tile 128, fused att+bias+tanh epilogue in SMEM.
// ===========================================================================
#define ASTR 40
#define STG_A  (96  * ASTR * 2)        // 7680 B
#define STG_B  (128 * ASTR * 2)        // 10240 B
#define STG_SZ (STG_A + STG_B)         // 17920 B
#define GEMM_SMEM (4 * STG_SZ)         // 71680 B (>= epilogue 59904)

__global__ void __launch_bounds__(256, 2)
layer_kernel(int layer, int residual, int emit,
             const float* __restrict__ att, const float* __restrict__ bias) {
    extern __shared__ __align__(16) char smem[];
    const int tid = threadIdx.x;
    const int lane = tid & 31, wid = tid >> 5;
    const int wm = wid >> 2, wn = wid & 3;
    const int n0 = blockIdx.x * 128;
    const int m0 = blockIdx.y * 96;
    const uint32_t sbase = smem_u32(smem);

    const __half* Af = g_Af;
    const __half* Wh = g_Wh + layer * 262144;

    float acc[3][4][4];
    #pragma unroll
    for (int i = 0; i < 3; i++)
        #pragma unroll
        for (int j = 0; j < 4; j++)
            #pragma unroll
            for (int r = 0; r < 4; r++) acc[i][j][r] = 0.f;

    #define LOAD_STAGE(buf, ks) do { \
        uint32_t stg = sbase + (buf) * STG_SZ; \
        _Pragma("unroll") \
        for (int it = 0; it < 4; it++) { \
            int i = it * 256 + tid; \
            if (it == 3 && tid >= 128) break; \
            int r = i >> 2, q = i & 3; \
            uint32_t dst; const __half* src; \
            if (r < 96) { \
                dst = stg + r * 80 + q * 16; \
                src = Af + (size_t)(m0 + r) * 512 + (ks) * 32 + q * 8; \
            } else { \
                dst = stg + STG_A + (r - 96) * 80 + q * 16; \
                src = Wh + (size_t)(n0 + r - 96) * 512 + (ks) * 32 + q * 8; \
            } \
            CPA16(dst, src); \
        } \
    } while (0)

    LOAD_STAGE(0, 0); CP_COMMIT();
    LOAD_STAGE(1, 1); CP_COMMIT();
    LOAD_STAGE(2, 2); CP_COMMIT();

    const int arow = wm * 48 + (lane & 15);
    const int acol = (lane >> 4) * 8;
    const int brow = wn * 32 + (lane & 7) + ((lane >> 4) & 1) * 8;
    const int bcol = ((lane >> 3) & 1) * 8;

    int buf = 0, ld = 3;
    #pragma unroll 1
    for (int ks = 0; ks < 16; ks++) {
        if (ks + 3 < 16) { CP_WAIT(2); } else { CP_WAIT(0); }
        __syncthreads();   // stage ks ready; all warps done MMAing buffer ld
        if (ks + 3 < 16) { LOAD_STAGE(ld, ks + 3); CP_COMMIT(); }

        uint32_t base = sbase + buf * STG_SZ;
        #pragma unroll
        for (int sub = 0; sub < 2; sub++) {
            int kb = sub * 16;
            uint32_t ah[3][4], bh[2][4];
            #pragma unroll
            for (int mt = 0; mt < 3; mt++)
                LDSM4(ah[mt], base + (uint32_t)((arow + mt * 16) * ASTR + kb + acol) * 2);
            #pragma unroll
            for (int ng = 0; ng < 2; ng++)
                LDSM4(bh[ng], base + STG_A + (uint32_t)((brow + ng * 16) * ASTR + kb + bcol) * 2);
            #pragma unroll
            for (int mt = 0; mt < 3; mt++) {
                #pragma unroll
                for (int nf = 0; nf < 4; nf++)
                    mma_f16(acc[mt][nf], ah[mt], &bh[nf >> 1][(nf & 1) * 2]);
            }
        }
        buf = (buf + 1) & 3;
        ld  = (ld  + 1) & 3;
    }
    __syncthreads();   // mainloop fully done before SMEM is repurposed

    // ================= fused epilogue: att @ G + bias + tanh ===============
    float* sG = (float*)smem;                 // 96*132*4 = 50688 B
    float* sAttT = sG + 96 * 132;             // + 9216 = 59904 <= 71680

    #pragma unroll
    for (int mt = 0; mt < 3; mt++) {
        int row = wm * 48 + mt * 16 + (lane >> 2);
        #pragma unroll
        for (int nf = 0; nf < 4; nf++) {
            int col = wn * 32 + nf * 8 + (lane & 3) * 2;
            sG[row * 132 + col]           = acc[mt][nf][0];
            sG[row * 132 + col + 1]       = acc[mt][nf][1];
            sG[(row + 8) * 132 + col]     = acc[mt][nf][2];
            sG[(row + 8) * 132 + col + 1] = acc[mt][nf][3];
        }
    }
    for (int i = tid; i < 2304; i += 256) {
        int m = i / 48, n = i % 48;
        sAttT[m * 48 + n] = __ldg(att + n * 48 + m);
    }
    __syncthreads();

    {
        const int lc = tid & 127;
        const int b2 = tid >> 7;
        float g[48];
        #pragma unroll
        for (int m = 0; m < 48; m++) g[m] = sG[(b2 * 48 + m) * 132 + lc];

        ull gacc[24];
        #pragma unroll
        for (int j = 0; j < 24; j++) gacc[j] = 0ull;
        #pragma unroll 4
        for (int m = 0; m < 48; m++) {
            ull gp = pk2(g[m], g[m]);
            const ull* ap = (const ull*)(sAttT + m * 48);
            #pragma unroll
            for (int j = 0; j < 24; j++) fma2f(gacc[j], ap[j], gp);
        }

        const int col = n0 + lc;
        const float bb = __ldg(bias + col);
        const size_t rowbase = (size_t)(m0 + b2 * 48) * 512 + col;
        #pragma unroll
        for (int j = 0; j < 24; j++) {
            float2 z = up2(gacc[j]);
            float v0 = ftanh(z.x + bb);
            float v1 = ftanh(z.y + bb);
            size_t i0 = rowbase + (size_t)(2 * j) * 512;
            size_t i1 = i0 + 512;
            if (residual) {
                v0 += g_X[i0];
                v1 += g_X[i1];
                g_X[i0] = v0;
                g_X[i1] = v1;
            }
            if (emit) {
                g_Af[i0] = __float2half_rn(v0);
                g_Af[i1] = __float2half_rn(v1);
            }
        }
    }
}

// ======================= tail: gc7 + fused + MLP (warp-dot) ================
#define TAIL_SMEM ((24576 + 5120 + 480 + 480 + 480 + 1920 + 2560) * 4)
__global__ void __launch_bounds__(512)
tail_kernel(const float* __restrict__ gc7_w, const float* __restrict__ gc7_att,
            const float* __restrict__ gc7_b, const float* __restrict__ mlp_w1,
            const float* __restrict__ mlp_w2, float* __restrict__ out) {
    extern __shared__ float sm[];
    float* sY    = sm;              // 24576 (reused as sH after P phase)
    float* sW7   = sm + 24576;      // 5120 [o][k]
    float* sDct  = sm + 29696;      // 480
    float* sP    = sm + 30176;      // 480
    float* sOut  = sm + 30656;      // 480
    float* sFused= sm + 31136;      // 1920
    float* sW2   = sm + 33056;      // 2560 [t2][o]
    float* sH    = sm;              // overlay

    const int tid = threadIdx.x, b = blockIdx.x;
    const int lane = tid & 31, w = tid >> 5;

    {
        const float4* ysrc = (const float4*)(g_X + (size_t)b * 24576);
        float4* ydst = (float4*)sY;
        #pragma unroll
        for (int i = 0; i < 12; i++) ydst[tid + i * 512] = ysrc[tid + i * 512];
    }
    for (int i = tid; i < 5120; i += 512) {
        int o = i >> 9, k = i & 511;
        sW7[i] = __ldg(gc7_w + k * 10 + o);
    }
    for (int i = tid; i < 2560; i += 512) sW2[i] = __ldg(mlp_w2 + i);
    if (tid < 480) sDct[tid] = g_dct[b * 480 + tid];
    __syncthreads();

    #pragma unroll 1
    for (int uu = 0; uu < 30; uu++) {
        int u = uu * 16 + w;
        int m = u / 10, o = u % 10;
        const float* yr = sY + m * 512;
        const float* wr = sW7 + o * 512;
        float a = 0.f;
        #pragma unroll
        for (int j = 0; j < 16; j++) a += yr[j * 32 + lane] * wr[j * 32 + lane];
        a += __shfl_xor_sync(0xFFFFFFFFu, a, 16);
        a += __shfl_xor_sync(0xFFFFFFFFu, a, 8);
        a += __shfl_xor_sync(0xFFFFFFFFu, a, 4);
        a += __shfl_xor_sync(0xFFFFFFFFu, a, 2);
        a += __shfl_xor_sync(0xFFFFFFFFu, a, 1);
        if (lane == 0) sP[u] = a;
    }
    __syncthreads();

    if (tid < 480) {
        int n = tid / 10, o = tid % 10;
        float a = __ldg(gc7_b + o) + sDct[tid];
        for (int m = 0; m < 48; m++) a += __ldg(gc7_att + n * 48 + m) * sP[m * 10 + o];
        sOut[tid] = a;
    }
    __syncthreads();

    for (int i = tid; i < 1920; i += 512) {
        int f = i % 48, t = i / 48;
        float v;
        if (t < 30) {
            v = 0.f;
            #pragma unroll
            for (int d = 0; d < 10; d++) {
                float wd = (d == 0) ? W0_DCT : W1_DCT;
                v += wd * cosf(PI_F * ((float)t + 0.5f) * (float)d / 30.0f)
                        * sOut[f * 10 + d];
            }
        } else v = g_ffc[b * 480 + f * 10 + (t - 30)];
        sFused[f * 40 + t] = v;
    }
    __syncthreads();

    {
        int o = tid & 255, fg = tid >> 8;
        float w1r[40];
        #pragma unroll
        for (int t = 0; t < 40; t++) w1r[t] = __ldg(mlp_w1 + o * 40 + t);
        for (int f = fg * 24; f < fg * 24 + 24; f++) {
            float a = 0.f;
            #pragma unroll
            for (int t = 0; t < 40; t++) a += w1r[t] * sFused[f * 40 + t];
            sH[f * 256 + o] = (a > 0.f) ? a : 0.f;
        }
    }
    __syncthreads();

    #pragma unroll 1
    for (int uu = 0; uu < 30; uu++) {
        int u = uu * 16 + w;
        int f = u / 10, t2 = u % 10;
        const float* hr = sH + f * 256;
        const float* wr = sW2 + t2 * 256;
        float a = 0.f;
        #pragma unroll
        for (int j = 0; j < 8; j++) a += hr[j * 32 + lane] * wr[j * 32 + lane];
        a += __shfl_xor_sync(0xFFFFFFFFu, a, 16);
        a += __shfl_xor_sync(0xFFFFFFFFu, a, 8);
        a += __shfl_xor_sync(0xFFFFFFFFu, a, 4);
        a += __shfl_xor_sync(0xFFFFFFFFu, a, 2);
        a += __shfl_xor_sync(0xFFFFFFFFu, a, 1);
        if (lane == 0) out[b * 480 + t2 * 48 + f] = a;
    }
}

// ===========================================================================
extern "C" void kernel_launch(void* const* d_in, const int* in_sizes, int n_in,
                              void* d_out, int out_size) {
    const float* seq     = (const float*)d_in[0];
    const float* gc1_w   = (const float*)d_in[5];
    const float* gc1_att = (const float*)d_in[6];
    const float* gc1_b   = (const float*)d_in[7];
    const float* gcb_w   = (const float*)d_in[8];
    const float* gcb_att = (const float*)d_in[9];
    const float* gcb_b   = (const float*)d_in[10];
    const float* gc7_w   = (const float*)d_in[11];
    const float* gc7_att = (const float*)d_in[12];
    const float* gc7_b   = (const float*)d_in[13];
    const float* mlp_w1  = (const float*)d_in[14];
    const float* mlp_w2  = (const float*)d_in[15];
    const float* ffc_wl  = (const float*)d_in[16];
    const float* ffc_wg  = (const float*)d_in[17];
    float* out = (float*)d_out;

    int B = in_sizes[0] / 2400;           // 1024
    int gm = (B * 48) / 96;               // 512 m-tiles

    cudaFuncSetAttribute(layer_kernel,
        cudaFuncAttributeMaxDynamicSharedMemorySize, GEMM_SMEM);
    cudaFuncSetAttribute(tail_kernel,
        cudaFuncAttributeMaxDynamicSharedMemorySize, TAIL_SMEM);

    prep_w_kernel<<<4096, 256>>>(gcb_w);
    head_kernel<<<B, 512>>>(seq, ffc_wl, ffc_wg, gc1_w, gc1_att, gc1_b);

    for (int l = 0; l < 4; l++) {
        layer_kernel<<<dim3(4, gm), 256, GEMM_SMEM>>>(
            l, l & 1, (l < 3) ? 1 : 0,
            gcb_att + l * 2304, gcb_b + l * 512);
    }
    tail_kernel<<<B, 512, TAIL_SMEM>>>(gc7_w, gc7_att, gc7_b,
                                       mlp_w1, mlp_w2, out);
}